// round 2
// baseline (speedup 1.0000x reference)
#include <cuda_runtime.h>

#define HEADS  16
#define HD     128
#define HIDDEN 2048
#define BB     4
#define SEQ    2048
#define NQKV   (3*HIDDEN)      // 6144
#define MTOT   (BB*SEQ)        // 8192

// scratch for qkv projection result: [8192, 6144] fp32 = 201 MB
__device__ float g_qkv[(size_t)MTOT * NQKV];

// ---------------------------------------------------------------------------
// QKV GEMM: C[m,n] = sum_k A[m,k]*W[k,n] + bias[n]
// A: [8192, 2048], W: [2048, 6144] row-major. Tile 128x128x16, 256 thr, 8x8/thr.
// ---------------------------------------------------------------------------
__global__ __launch_bounds__(256) void qkv_gemm(const float* __restrict__ A,
                                                const float* __restrict__ W,
                                                const float* __restrict__ bias) {
    __shared__ float As[16][128];   // transposed: As[k][m]
    __shared__ float Bs[16][128];   // Bs[k][n]

    const int tid = threadIdx.x;
    const int tx = tid & 15, ty = tid >> 4;
    const int bm = blockIdx.y << 7, bn = blockIdx.x << 7;

    float acc[8][8];
#pragma unroll
    for (int i = 0; i < 8; ++i)
#pragma unroll
        for (int j = 0; j < 8; ++j) acc[i][j] = 0.0f;

    for (int k0 = 0; k0 < HIDDEN; k0 += 16) {
        // load A tile (128 rows x 16 k): 512 float4
#pragma unroll
        for (int f = tid; f < 512; f += 256) {
            int r = f >> 2, kc = (f & 3) << 2;
            float4 v = *reinterpret_cast<const float4*>(
                &A[(size_t)(bm + r) * HIDDEN + k0 + kc]);
            As[kc + 0][r] = v.x; As[kc + 1][r] = v.y;
            As[kc + 2][r] = v.z; As[kc + 3][r] = v.w;
        }
        // load B tile (16 k x 128 n): 512 float4, coalesced
#pragma unroll
        for (int f = tid; f < 512; f += 256) {
            int r = f >> 5, c = (f & 31) << 2;
            *reinterpret_cast<float4*>(&Bs[r][c]) =
                *reinterpret_cast<const float4*>(&W[(size_t)(k0 + r) * NQKV + bn + c]);
        }
        __syncthreads();
#pragma unroll
        for (int kk = 0; kk < 16; ++kk) {
            float a[8], b[8];
            *reinterpret_cast<float4*>(&a[0]) = *reinterpret_cast<float4*>(&As[kk][ty << 2]);
            *reinterpret_cast<float4*>(&a[4]) = *reinterpret_cast<float4*>(&As[kk][64 + (ty << 2)]);
            *reinterpret_cast<float4*>(&b[0]) = *reinterpret_cast<float4*>(&Bs[kk][tx << 2]);
            *reinterpret_cast<float4*>(&b[4]) = *reinterpret_cast<float4*>(&Bs[kk][64 + (tx << 2)]);
#pragma unroll
            for (int i = 0; i < 8; ++i)
#pragma unroll
                for (int j = 0; j < 8; ++j)
                    acc[i][j] += a[i] * b[j];
        }
        __syncthreads();
    }
    // epilogue: rows ty*4+(i&3) + (i>>2)*64, cols tx*4+(j&3) + (j>>2)*64
#pragma unroll
    for (int i = 0; i < 8; ++i) {
        int r = bm + (ty << 2) + (i & 3) + ((i >> 2) << 6);
#pragma unroll
        for (int jj = 0; jj < 2; ++jj) {
            int c = bn + (tx << 2) + (jj << 6);
            float4 o;
            o.x = acc[i][jj * 4 + 0] + bias[c + 0];
            o.y = acc[i][jj * 4 + 1] + bias[c + 1];
            o.z = acc[i][jj * 4 + 2] + bias[c + 2];
            o.w = acc[i][jj * 4 + 3] + bias[c + 3];
            *reinterpret_cast<float4*>(&g_qkv[(size_t)r * NQKV + c]) = o;
        }
    }
}

// ---------------------------------------------------------------------------
// Flash attention: one block per (b, h, q-tile of 64). BK=64 key tiles.
// Online softmax, O accumulator in registers. Jagged masking via lengths.
// ---------------------------------------------------------------------------
#define QK_STRIDE 132
#define SC_STRIDE 65
#define ATTN_SMEM_FLOATS (64*QK_STRIDE + 64*QK_STRIDE + 64*HD + 64*SC_STRIDE)
#define ATTN_SMEM_BYTES  (ATTN_SMEM_FLOATS * 4)

__global__ __launch_bounds__(256) void attn_kernel(const void* __restrict__ lens_raw,
                                                   float* __restrict__ out) {
    extern __shared__ float sm[];
    float* Qs = sm;
    float* Ks = Qs + 64 * QK_STRIDE;
    float* Vs = Ks + 64 * QK_STRIDE;
    float* Sc = Vs + 64 * HD;

    const int b = blockIdx.z, h = blockIdx.y;
    const int q0 = blockIdx.x << 6;
    const int tid = threadIdx.x;

    // lengths dtype sniff: int64 layout has high word 0; int32 has lengths[1]=1024!=0
    const int* li = (const int*)lens_raw;
    int L = (li[1] == 0) ? li[2 * b] : li[b];
    if (L > SEQ) L = SEQ;
    if (L < 0) L = 0;

    const int orow = tid >> 2, ocg = tid & 3;   // O-accum mapping: row, col-group
    float* obase = out + ((size_t)(b * HEADS + h) * SEQ) * HD;

    if (q0 >= L) {  // whole tile is padded queries -> zeros
        float4 z = make_float4(0.f, 0.f, 0.f, 0.f);
        float* op = obase + (size_t)(q0 + orow) * HD + (ocg << 2);
#pragma unroll
        for (int cc = 0; cc < 8; ++cc)
            *reinterpret_cast<float4*>(op + (cc << 4)) = z;
        return;
    }

    const float* qbase = g_qkv + (size_t)(b * SEQ) * NQKV + h * HD;
    const float* kbase = qbase + HIDDEN;
    const float* vbase = qbase + 2 * HIDDEN;

    // load Q tile (64 x 128)
    for (int f = tid; f < 64 * 32; f += 256) {
        int r = f >> 5, c4 = (f & 31) << 2;
        *reinterpret_cast<float4*>(&Qs[r * QK_STRIDE + c4]) =
            *reinterpret_cast<const float4*>(&qbase[(size_t)(q0 + r) * NQKV + c4]);
    }

    float4 accO[8];
#pragma unroll
    for (int cc = 0; cc < 8; ++cc) accO[cc] = make_float4(0.f, 0.f, 0.f, 0.f);
    float mrun = -1e30f, lrun = 0.0f;
    const float scale = 0.088388347648318447f;   // 1/sqrt(128)

    const int sy = tid >> 4, sx = tid & 15;      // score-phase mapping

    const int nkt = (L + 63) >> 6;
    for (int t = 0; t < nkt; ++t) {
        const int k0 = t << 6;
        const int valid = L - k0;                // > 0 by construction
        __syncthreads();                         // prev-iter smem reads done
        // load K, V tiles (zero padded keys)
        for (int f = tid; f < 64 * 32; f += 256) {
            int r = f >> 5, c4 = (f & 31) << 2;
            float4 kv, vv;
            if (k0 + r < L) {
                kv = *reinterpret_cast<const float4*>(&kbase[(size_t)(k0 + r) * NQKV + c4]);
                vv = *reinterpret_cast<const float4*>(&vbase[(size_t)(k0 + r) * NQKV + c4]);
            } else {
                kv = make_float4(0.f, 0.f, 0.f, 0.f);
                vv = kv;
            }
            *reinterpret_cast<float4*>(&Ks[r * QK_STRIDE + c4]) = kv;
            *reinterpret_cast<float4*>(&Vs[r * HD + c4]) = vv;
        }
        __syncthreads();
        // scores: each thread 4 rows (sy*4+a) x 4 cols (sx + 16*c)
        float sc[4][4];
#pragma unroll
        for (int a = 0; a < 4; ++a)
#pragma unroll
            for (int c = 0; c < 4; ++c) sc[a][c] = 0.0f;
        for (int k = 0; k < HD; k += 4) {
            float4 qv[4], kv[4];
#pragma unroll
            for (int a = 0; a < 4; ++a)
                qv[a] = *reinterpret_cast<const float4*>(&Qs[((sy << 2) + a) * QK_STRIDE + k]);
#pragma unroll
            for (int c = 0; c < 4; ++c)
                kv[c] = *reinterpret_cast<const float4*>(&Ks[(sx + (c << 4)) * QK_STRIDE + k]);
#pragma unroll
            for (int a = 0; a < 4; ++a)
#pragma unroll
                for (int c = 0; c < 4; ++c)
                    sc[a][c] += qv[a].x * kv[c].x + qv[a].y * kv[c].y +
                                qv[a].z * kv[c].z + qv[a].w * kv[c].w;
        }
#pragma unroll
        for (int a = 0; a < 4; ++a)
#pragma unroll
            for (int c = 0; c < 4; ++c)
                Sc[((sy << 2) + a) * SC_STRIDE + sx + (c << 4)] = sc[a][c] * scale;
        __syncthreads();
        // online softmax: 4 threads per row (orow), cols [ocg*16, ocg*16+16)
        float sv[16];
        float tmax = -1e30f;
#pragma unroll
        for (int jj = 0; jj < 16; ++jj) {
            int j = (ocg << 4) + jj;
            float v = (j < valid) ? Sc[orow * SC_STRIDE + j] : -1e30f;
            sv[jj] = v;
            tmax = fmaxf(tmax, v);
        }
        tmax = fmaxf(tmax, __shfl_xor_sync(0xffffffffu, tmax, 1));
        tmax = fmaxf(tmax, __shfl_xor_sync(0xffffffffu, tmax, 2));
        float mnew  = fmaxf(mrun, tmax);
        float alpha = __expf(mrun - mnew);
        float lsum = 0.0f;
#pragma unroll
        for (int jj = 0; jj < 16; ++jj) {
            float p = __expf(sv[jj] - mnew);      // exactly 0 for masked (-1e30)
            Sc[orow * SC_STRIDE + (ocg << 4) + jj] = p;
            lsum += p;
        }
        lsum += __shfl_xor_sync(0xffffffffu, lsum, 1);
        lsum += __shfl_xor_sync(0xffffffffu, lsum, 2);
        lrun = lrun * alpha + lsum;
        mrun = mnew;
#pragma unroll
        for (int cc = 0; cc < 8; ++cc) {
            accO[cc].x *= alpha; accO[cc].y *= alpha;
            accO[cc].z *= alpha; accO[cc].w *= alpha;
        }
        __syncthreads();   // p values visible to all threads of the row
        // O += P @ V : thread owns row orow, 8 float4 cols at ocg*4 + 16*cc
#pragma unroll 4
        for (int j = 0; j < 64; ++j) {
            float p = Sc[orow * SC_STRIDE + j];
#pragma unroll
            for (int cc = 0; cc < 8; ++cc) {
                float4 v = *reinterpret_cast<const float4*>(
                    &Vs[j * HD + (ocg << 2) + (cc << 4)]);
                accO[cc].x += p * v.x; accO[cc].y += p * v.y;
                accO[cc].z += p * v.z; accO[cc].w += p * v.w;
            }
        }
    }
    // epilogue: normalize; zero padded query rows
    float inv = 1.0f / lrun;
    bool rvalid = (q0 + orow) < L;
    float* op = obase + (size_t)(q0 + orow) * HD + (ocg << 2);
#pragma unroll
    for (int cc = 0; cc < 8; ++cc) {
        float4 o;
        if (rvalid) {
            o.x = accO[cc].x * inv; o.y = accO[cc].y * inv;
            o.z = accO[cc].z * inv; o.w = accO[cc].w * inv;
        } else {
            o = make_float4(0.f, 0.f, 0.f, 0.f);
        }
        *reinterpret_cast<float4*>(op + (cc << 4)) = o;
    }
}

// ---------------------------------------------------------------------------
extern "C" void kernel_launch(void* const* d_in, const int* in_sizes, int n_in,
                              void* d_out, int out_size) {
    const float* x    = (const float*)d_in[0];   // [4, 2048, 2048]
    const float* W    = (const float*)d_in[1];   // [2048, 6144]
    const float* bias = (const float*)d_in[2];   // [6144]
    const void*  lens = d_in[3];                 // [4] int64 (or int32)
    float* out = (float*)d_out;                  // [4, 16, 2048, 128]

    cudaFuncSetAttribute(attn_kernel, cudaFuncAttributeMaxDynamicSharedMemorySize,
                         ATTN_SMEM_BYTES);

    qkv_gemm<<<dim3(NQKV / 128, MTOT / 128), 256>>>(x, W, bias);
    attn_kernel<<<dim3(SEQ / 64, HEADS, BB), 256, ATTN_SMEM_BYTES>>>(lens, out);
}

// round 4
// speedup vs baseline: 1.4559x; 1.4559x over previous
#include <cuda_runtime.h>
#include <cuda_bf16.h>
#include <cstdint>

#define HEADS  16
#define HD     128
#define HIDDEN 2048
#define BB     4
#define SEQ    2048
#define NQKV   (3*HIDDEN)      // 6144
#define MTOT   (BB*SEQ)        // 8192

// ---------------------------------------------------------------------------
// Scratch (device globals; no allocation allowed)
// ---------------------------------------------------------------------------
__device__ float g_qkv[(size_t)MTOT * NQKV];                  // 201 MB
__device__ __nv_bfloat16 g_xh[(size_t)MTOT * HIDDEN];         // hi plane of x
__device__ __nv_bfloat16 g_xl[(size_t)MTOT * HIDDEN];         // lo plane of x
__device__ __nv_bfloat16 g_wth[(size_t)NQKV * HIDDEN];        // W^T hi  [N,K]
__device__ __nv_bfloat16 g_wtl[(size_t)NQKV * HIDDEN];        // W^T lo  [N,K]

// ---------------------------------------------------------------------------
// sm_80-level tensor-core primitives (valid on plain sm_103 target)
// ---------------------------------------------------------------------------
__device__ __forceinline__ uint32_t smem_u32(const void* p) {
    uint32_t a;
    asm("{ .reg .u64 t; cvta.to.shared.u64 t, %1; cvt.u32.u64 %0, t; }" : "=r"(a) : "l"(p));
    return a;
}
__device__ __forceinline__ void ldsm4(uint32_t* r, uint32_t addr) {
    asm volatile("ldmatrix.sync.aligned.m8n8.x4.shared.b16 {%0,%1,%2,%3}, [%4];"
        : "=r"(r[0]), "=r"(r[1]), "=r"(r[2]), "=r"(r[3]) : "r"(addr));
}
__device__ __forceinline__ void mma_bf16(float* d, const uint32_t* a, const uint32_t* b) {
    asm volatile("mma.sync.aligned.m16n8k16.row.col.f32.bf16.bf16.f32 "
        "{%0,%1,%2,%3}, {%4,%5,%6,%7}, {%8,%9}, {%0,%1,%2,%3};"
        : "+f"(d[0]), "+f"(d[1]), "+f"(d[2]), "+f"(d[3])
        : "r"(a[0]), "r"(a[1]), "r"(a[2]), "r"(a[3]), "r"(b[0]), "r"(b[1]));
}
#define CP_ASYNC16(dst, src) \
    asm volatile("cp.async.cg.shared.global [%0], [%1], 16;" :: "r"(dst), "l"(src))
#define CP_COMMIT() asm volatile("cp.async.commit_group;" ::: "memory")
#define CP_WAIT1()  asm volatile("cp.async.wait_group 1;" ::: "memory")
#define CP_WAIT0()  asm volatile("cp.async.wait_group 0;" ::: "memory")

// ---------------------------------------------------------------------------
// Prep 1: x (fp32) -> hi/lo bf16 planes
// ---------------------------------------------------------------------------
__global__ __launch_bounds__(256) void conv_x(const float* __restrict__ x) {
    size_t i = ((size_t)blockIdx.x * 256 + threadIdx.x) * 4;
    float4 v = *reinterpret_cast<const float4*>(x + i);
    __nv_bfloat16 h0 = __float2bfloat16(v.x), h1 = __float2bfloat16(v.y);
    __nv_bfloat16 h2 = __float2bfloat16(v.z), h3 = __float2bfloat16(v.w);
    __nv_bfloat16 l0 = __float2bfloat16(v.x - __bfloat162float(h0));
    __nv_bfloat16 l1 = __float2bfloat16(v.y - __bfloat162float(h1));
    __nv_bfloat16 l2 = __float2bfloat16(v.z - __bfloat162float(h2));
    __nv_bfloat16 l3 = __float2bfloat16(v.w - __bfloat162float(h3));
    reinterpret_cast<__nv_bfloat162*>(g_xh + i)[0] = __halves2bfloat162(h0, h1);
    reinterpret_cast<__nv_bfloat162*>(g_xh + i)[1] = __halves2bfloat162(h2, h3);
    reinterpret_cast<__nv_bfloat162*>(g_xl + i)[0] = __halves2bfloat162(l0, l1);
    reinterpret_cast<__nv_bfloat162*>(g_xl + i)[1] = __halves2bfloat162(l2, l3);
}

// ---------------------------------------------------------------------------
// Prep 2: W [K=2048, N=6144] -> W^T hi/lo planes [6144, 2048] bf16 (tiled)
// ---------------------------------------------------------------------------
__global__ __launch_bounds__(256) void conv_wt(const float* __restrict__ W) {
    __shared__ float tile[32][33];
    const int n0 = blockIdx.x * 32, k0 = blockIdx.y * 32;
    const int tx = threadIdx.x, ty = threadIdx.y;   // (32, 8)
#pragma unroll
    for (int i = 0; i < 4; ++i)
        tile[ty + 8 * i][tx] = W[(size_t)(k0 + ty + 8 * i) * NQKV + n0 + tx];
    __syncthreads();
#pragma unroll
    for (int i = 0; i < 4; ++i) {
        int n = ty + 8 * i;
        float v = tile[tx][n];                       // = W[k0+tx][n0+n]
        __nv_bfloat16 h = __float2bfloat16(v);
        __nv_bfloat16 l = __float2bfloat16(v - __bfloat162float(h));
        g_wth[(size_t)(n0 + n) * HIDDEN + k0 + tx] = h;
        g_wtl[(size_t)(n0 + n) * HIDDEN + k0 + tx] = l;
    }
}

// ---------------------------------------------------------------------------
// mma.sync bf16 GEMM, 3-pass hi/lo split. CTA 128x128, k-chunk 32, 8 warps
// (each 64m x 32n), cp.async double buffer, 80B smem row stride
// (conflict-free ldmatrix: (20*r) mod 32 spans all banks for r=0..7).
// ---------------------------------------------------------------------------
#define PLANE 10240                 // 128 rows * 80 B
#define BUFSZ (4 * PLANE)           // Ahi | Alo | Bhi | Blo
#define GM_SMEM_TOTAL (2 * BUFSZ)   // 81920

__global__ __launch_bounds__(256, 1) void qkv_gemm_tc(const float* __restrict__ bias) {
    extern __shared__ char smem[];
    const uint32_t sb = smem_u32(smem);
    const int tid = threadIdx.x;
    const int wid = tid >> 5, lane = tid & 31;
    const int bn = blockIdx.x << 7, bm = blockIdx.y << 7;

    const int wmb = (wid & 1) << 6;     // warp m base (0/64)
    const int wnb = (wid >> 1) << 5;    // warp n base (0/32/64/96)

    float acc[4][4][4];
#pragma unroll
    for (int mt = 0; mt < 4; ++mt)
#pragma unroll
        for (int nt = 0; nt < 4; ++nt)
#pragma unroll
            for (int q = 0; q < 4; ++q) acc[mt][nt][q] = 0.0f;

    // ---- async loader: chunk c = 32 bf16 of K into buffer c&1 ----
    auto load_chunk = [&](int c) {
        const int b = c & 1;
        const int k0 = c << 5;
        const uint32_t base = sb + b * BUFSZ;
#pragma unroll
        for (int i = 0; i < 8; ++i) {
            const int f = tid + (i << 8);          // 0..2047
            const int t = f >> 9;                  // plane
            const int rc = f & 511;
            const int r = rc >> 2, j = rc & 3;     // row, 16B chunk
            const __nv_bfloat16* src;
            if (t == 0)      src = g_xh  + (size_t)(bm + r) * HIDDEN + k0 + j * 8;
            else if (t == 1) src = g_xl  + (size_t)(bm + r) * HIDDEN + k0 + j * 8;
            else if (t == 2) src = g_wth + (size_t)(bn + r) * HIDDEN + k0 + j * 8;
            else             src = g_wtl + (size_t)(bn + r) * HIDDEN + k0 + j * 8;
            CP_ASYNC16(base + t * PLANE + r * 80 + j * 16, src);
        }
        CP_COMMIT();
    };

    load_chunk(0);
    load_chunk(1);

    // ldmatrix lane addressing (byte offsets within plane)
    const int arow = wmb + (lane & 15);
    const int akoff = (lane >> 4) << 4;                     // 0 / 16
    const int brow = wnb + ((lane >> 4) << 3) + (lane & 7);
    const int bkoff = ((lane >> 3) & 1) << 4;               // 0 / 16

    for (int c = 0; c < 64; ++c) {
        const int b = c & 1;
        if (c == 63) { CP_WAIT0(); } else { CP_WAIT1(); }
        __syncthreads();
        const uint32_t Ah = sb + b * BUFSZ;
        const uint32_t Al = Ah + PLANE;
        const uint32_t Bh = Al + PLANE;
        const uint32_t Bl = Bh + PLANE;
#pragma unroll
        for (int s = 0; s < 2; ++s) {              // two k16 steps per chunk
            uint32_t ah[4][4], al[4][4], bh[2][4], bl[2][4];
            const int sk = s << 5;                 // +32B per k16
#pragma unroll
            for (int mt = 0; mt < 4; ++mt) {
                const uint32_t off = (uint32_t)((arow + (mt << 4)) * 80) + akoff + sk;
                ldsm4(ah[mt], Ah + off);
                ldsm4(al[mt], Al + off);
            }
#pragma unroll
            for (int p = 0; p < 2; ++p) {          // each x4 covers 2 n-tiles
                const uint32_t off = (uint32_t)((brow + (p << 4)) * 80) + bkoff + sk;
                ldsm4(bh[p], Bh + off);
                ldsm4(bl[p], Bl + off);
            }
#pragma unroll
            for (int mt = 0; mt < 4; ++mt)
#pragma unroll
                for (int nt = 0; nt < 4; ++nt) {
                    const uint32_t* bhp = &bh[nt >> 1][(nt & 1) * 2];
                    const uint32_t* blp = &bl[nt >> 1][(nt & 1) * 2];
                    mma_bf16(acc[mt][nt], ah[mt], bhp);   // hi*hi
                    mma_bf16(acc[mt][nt], ah[mt], blp);   // hi*lo
                    mma_bf16(acc[mt][nt], al[mt], bhp);   // lo*hi
                }
        }
        __syncthreads();
        if (c + 2 < 64) load_chunk(c + 2);
    }

    // ---- epilogue: add bias, store fp32 ----
    const int m0 = bm + wmb + (lane >> 2);
    const int n0 = bn + wnb + ((lane & 3) << 1);
#pragma unroll
    for (int mt = 0; mt < 4; ++mt) {
#pragma unroll
        for (int nt = 0; nt < 4; ++nt) {
            const int m = m0 + (mt << 4);
            const int n = n0 + (nt << 3);
            const float b0 = bias[n], b1 = bias[n + 1];
            float2 v0 = make_float2(acc[mt][nt][0] + b0, acc[mt][nt][1] + b1);
            float2 v1 = make_float2(acc[mt][nt][2] + b0, acc[mt][nt][3] + b1);
            *reinterpret_cast<float2*>(&g_qkv[(size_t)m * NQKV + n]) = v0;
            *reinterpret_cast<float2*>(&g_qkv[(size_t)(m + 8) * NQKV + n]) = v1;
        }
    }
}

// ---------------------------------------------------------------------------
// Flash attention (unchanged known-good fp32 version)
// ---------------------------------------------------------------------------
#define QK_STRIDE 132
#define SC_STRIDE 65
#define ATTN_SMEM_FLOATS (64*QK_STRIDE + 64*QK_STRIDE + 64*HD + 64*SC_STRIDE)
#define ATTN_SMEM_BYTES  (ATTN_SMEM_FLOATS * 4)

__global__ __launch_bounds__(256) void attn_kernel(const void* __restrict__ lens_raw,
                                                   float* __restrict__ out) {
    extern __shared__ float sm[];
    float* Qs = sm;
    float* Ks = Qs + 64 * QK_STRIDE;
    float* Vs = Ks + 64 * QK_STRIDE;
    float* Sc = Vs + 64 * HD;

    const int b = blockIdx.z, h = blockIdx.y;
    const int q0 = blockIdx.x << 6;
    const int tid = threadIdx.x;

    const int* li = (const int*)lens_raw;
    int L = (li[1] == 0) ? li[2 * b] : li[b];
    if (L > SEQ) L = SEQ;
    if (L < 0) L = 0;

    const int orow = tid >> 2, ocg = tid & 3;
    float* obase = out + ((size_t)(b * HEADS + h) * SEQ) * HD;

    if (q0 >= L) {
        float4 z = make_float4(0.f, 0.f, 0.f, 0.f);
        float* op = obase + (size_t)(q0 + orow) * HD + (ocg << 2);
#pragma unroll
        for (int cc = 0; cc < 8; ++cc)
            *reinterpret_cast<float4*>(op + (cc << 4)) = z;
        return;
    }

    const float* qbase = g_qkv + (size_t)(b * SEQ) * NQKV + h * HD;
    const float* kbase = qbase + HIDDEN;
    const float* vbase = qbase + 2 * HIDDEN;

    for (int f = tid; f < 64 * 32; f += 256) {
        int r = f >> 5, c4 = (f & 31) << 2;
        *reinterpret_cast<float4*>(&Qs[r * QK_STRIDE + c4]) =
            *reinterpret_cast<const float4*>(&qbase[(size_t)(q0 + r) * NQKV + c4]);
    }

    float4 accO[8];
#pragma unroll
    for (int cc = 0; cc < 8; ++cc) accO[cc] = make_float4(0.f, 0.f, 0.f, 0.f);
    float mrun = -1e30f, lrun = 0.0f;
    const float scale = 0.088388347648318447f;

    const int sy = tid >> 4, sx = tid & 15;

    const int nkt = (L + 63) >> 6;
    for (int t = 0; t < nkt; ++t) {
        const int k0 = t << 6;
        const int valid = L - k0;
        __syncthreads();
        for (int f = tid; f < 64 * 32; f += 256) {
            int r = f >> 5, c4 = (f & 31) << 2;
            float4 kv, vv;
            if (k0 + r < L) {
                kv = *reinterpret_cast<const float4*>(&kbase[(size_t)(k0 + r) * NQKV + c4]);
                vv = *reinterpret_cast<const float4*>(&vbase[(size_t)(k0 + r) * NQKV + c4]);
            } else {
                kv = make_float4(0.f, 0.f, 0.f, 0.f);
                vv = kv;
            }
            *reinterpret_cast<float4*>(&Ks[r * QK_STRIDE + c4]) = kv;
            *reinterpret_cast<float4*>(&Vs[r * HD + c4]) = vv;
        }
        __syncthreads();
        float sc[4][4];
#pragma unroll
        for (int a = 0; a < 4; ++a)
#pragma unroll
            for (int c = 0; c < 4; ++c) sc[a][c] = 0.0f;
        for (int k = 0; k < HD; k += 4) {
            float4 qv[4], kv[4];
#pragma unroll
            for (int a = 0; a < 4; ++a)
                qv[a] = *reinterpret_cast<const float4*>(&Qs[((sy << 2) + a) * QK_STRIDE + k]);
#pragma unroll
            for (int c = 0; c < 4; ++c)
                kv[c] = *reinterpret_cast<const float4*>(&Ks[(sx + (c << 4)) * QK_STRIDE + k]);
#pragma unroll
            for (int a = 0; a < 4; ++a)
#pragma unroll
                for (int c = 0; c < 4; ++c)
                    sc[a][c] += qv[a].x * kv[c].x + qv[a].y * kv[c].y +
                                qv[a].z * kv[c].z + qv[a].w * kv[c].w;
        }
#pragma unroll
        for (int a = 0; a < 4; ++a)
#pragma unroll
            for (int c = 0; c < 4; ++c)
                Sc[((sy << 2) + a) * SC_STRIDE + sx + (c << 4)] = sc[a][c] * scale;
        __syncthreads();
        float sv[16];
        float tmax = -1e30f;
#pragma unroll
        for (int jj = 0; jj < 16; ++jj) {
            int j = (ocg << 4) + jj;
            float v = (j < valid) ? Sc[orow * SC_STRIDE + j] : -1e30f;
            sv[jj] = v;
            tmax = fmaxf(tmax, v);
        }
        tmax = fmaxf(tmax, __shfl_xor_sync(0xffffffffu, tmax, 1));
        tmax = fmaxf(tmax, __shfl_xor_sync(0xffffffffu, tmax, 2));
        float mnew  = fmaxf(mrun, tmax);
        float alpha = __expf(mrun - mnew);
        float lsum = 0.0f;
#pragma unroll
        for (int jj = 0; jj < 16; ++jj) {
            float p = __expf(sv[jj] - mnew);
            Sc[orow * SC_STRIDE + (ocg << 4) + jj] = p;
            lsum += p;
        }
        lsum += __shfl_xor_sync(0xffffffffu, lsum, 1);
        lsum += __shfl_xor_sync(0xffffffffu, lsum, 2);
        lrun = lrun * alpha + lsum;
        mrun = mnew;
#pragma unroll
        for (int cc = 0; cc < 8; ++cc) {
            accO[cc].x *= alpha; accO[cc].y *= alpha;
            accO[cc].z *= alpha; accO[cc].w *= alpha;
        }
        __syncthreads();
#pragma unroll 4
        for (int j = 0; j < 64; ++j) {
            float p = Sc[orow * SC_STRIDE + j];
#pragma unroll
            for (int cc = 0; cc < 8; ++cc) {
                float4 v = *reinterpret_cast<const float4*>(
                    &Vs[j * HD + (ocg << 2) + (cc << 4)]);
                accO[cc].x += p * v.x; accO[cc].y += p * v.y;
                accO[cc].z += p * v.z; accO[cc].w += p * v.w;
            }
        }
    }
    float inv = 1.0f / lrun;
    bool rvalid = (q0 + orow) < L;
    float* op = obase + (size_t)(q0 + orow) * HD + (ocg << 2);
#pragma unroll
    for (int cc = 0; cc < 8; ++cc) {
        float4 o;
        if (rvalid) {
            o.x = accO[cc].x * inv; o.y = accO[cc].y * inv;
            o.z = accO[cc].z * inv; o.w = accO[cc].w * inv;
        } else {
            o = make_float4(0.f, 0.f, 0.f, 0.f);
        }
        *reinterpret_cast<float4*>(op + (cc << 4)) = o;
    }
}

// ---------------------------------------------------------------------------
extern "C" void kernel_launch(void* const* d_in, const int* in_sizes, int n_in,
                              void* d_out, int out_size) {
    const float* x    = (const float*)d_in[0];   // [4, 2048, 2048]
    const float* W    = (const float*)d_in[1];   // [2048, 6144]
    const float* bias = (const float*)d_in[2];   // [6144]
    const void*  lens = d_in[3];                 // [4] int64 (or int32)
    float* out = (float*)d_out;                  // [4, 16, 2048, 128]

    cudaFuncSetAttribute(qkv_gemm_tc, cudaFuncAttributeMaxDynamicSharedMemorySize,
                         GM_SMEM_TOTAL);
    cudaFuncSetAttribute(attn_kernel, cudaFuncAttributeMaxDynamicSharedMemorySize,
                         ATTN_SMEM_BYTES);

    conv_x<<<(MTOT * HIDDEN) / (256 * 4), 256>>>(x);
    conv_wt<<<dim3(NQKV / 32, HIDDEN / 32), dim3(32, 8)>>>(W);
    qkv_gemm_tc<<<dim3(NQKV / 128, MTOT / 128), 256, GM_SMEM_TOTAL>>>(bias);
    attn_kernel<<<dim3(SEQ / 64, HEADS, BB), 256, ATTN_SMEM_BYTES>>>(lens, out);
}

// round 5
// speedup vs baseline: 2.6320x; 1.8078x over previous
#include <cuda_runtime.h>
#include <cuda_bf16.h>
#include <cstdint>

#define HEADS  16
#define HD     128
#define HIDDEN 2048
#define BB     4
#define SEQ    2048
#define NQKV   (3*HIDDEN)      // 6144
#define MTOT   (BB*SEQ)        // 8192

// ---------------------------------------------------------------------------
// Scratch (device globals; no allocation allowed)
// ---------------------------------------------------------------------------
__device__ __nv_bfloat16 g_qh[(size_t)MTOT * NQKV];           // qkv hi plane
__device__ __nv_bfloat16 g_ql[(size_t)MTOT * NQKV];           // qkv lo plane
__device__ __nv_bfloat16 g_xh[(size_t)MTOT * HIDDEN];         // x hi
__device__ __nv_bfloat16 g_xl[(size_t)MTOT * HIDDEN];         // x lo
__device__ __nv_bfloat16 g_wth[(size_t)NQKV * HIDDEN];        // W^T hi [N,K]
__device__ __nv_bfloat16 g_wtl[(size_t)NQKV * HIDDEN];        // W^T lo [N,K]

// ---------------------------------------------------------------------------
// sm_80-level tensor-core primitives (valid on plain sm_103 target)
// ---------------------------------------------------------------------------
__device__ __forceinline__ uint32_t smem_u32(const void* p) {
    uint32_t a;
    asm("{ .reg .u64 t; cvta.to.shared.u64 t, %1; cvt.u32.u64 %0, t; }" : "=r"(a) : "l"(p));
    return a;
}
__device__ __forceinline__ void ldsm4(uint32_t* r, uint32_t addr) {
    asm volatile("ldmatrix.sync.aligned.m8n8.x4.shared.b16 {%0,%1,%2,%3}, [%4];"
        : "=r"(r[0]), "=r"(r[1]), "=r"(r[2]), "=r"(r[3]) : "r"(addr));
}
__device__ __forceinline__ void ldsm4t(uint32_t* r, uint32_t addr) {
    asm volatile("ldmatrix.sync.aligned.m8n8.x4.trans.shared.b16 {%0,%1,%2,%3}, [%4];"
        : "=r"(r[0]), "=r"(r[1]), "=r"(r[2]), "=r"(r[3]) : "r"(addr));
}
__device__ __forceinline__ void mma_bf16(float* d, const uint32_t* a, const uint32_t* b) {
    asm volatile("mma.sync.aligned.m16n8k16.row.col.f32.bf16.bf16.f32 "
        "{%0,%1,%2,%3}, {%4,%5,%6,%7}, {%8,%9}, {%0,%1,%2,%3};"
        : "+f"(d[0]), "+f"(d[1]), "+f"(d[2]), "+f"(d[3])
        : "r"(a[0]), "r"(a[1]), "r"(a[2]), "r"(a[3]), "r"(b[0]), "r"(b[1]));
}
#define CP_ASYNC16(dst, src) \
    asm volatile("cp.async.cg.shared.global [%0], [%1], 16;" :: "r"(dst), "l"(src))
#define CP_COMMIT() asm volatile("cp.async.commit_group;" ::: "memory")
#define CP_WAIT1()  asm volatile("cp.async.wait_group 1;" ::: "memory")
#define CP_WAIT0()  asm volatile("cp.async.wait_group 0;" ::: "memory")

__device__ __forceinline__ uint32_t packbf2(float x, float y) {
    __nv_bfloat162 t = __floats2bfloat162_rn(x, y);
    return *reinterpret_cast<uint32_t*>(&t);
}

// ---------------------------------------------------------------------------
// Prep 1: x (fp32) -> hi/lo bf16 planes
// ---------------------------------------------------------------------------
__global__ __launch_bounds__(256) void conv_x(const float* __restrict__ x) {
    size_t i = ((size_t)blockIdx.x * 256 + threadIdx.x) * 4;
    float4 v = *reinterpret_cast<const float4*>(x + i);
    __nv_bfloat16 h0 = __float2bfloat16(v.x), h1 = __float2bfloat16(v.y);
    __nv_bfloat16 h2 = __float2bfloat16(v.z), h3 = __float2bfloat16(v.w);
    __nv_bfloat16 l0 = __float2bfloat16(v.x - __bfloat162float(h0));
    __nv_bfloat16 l1 = __float2bfloat16(v.y - __bfloat162float(h1));
    __nv_bfloat16 l2 = __float2bfloat16(v.z - __bfloat162float(h2));
    __nv_bfloat16 l3 = __float2bfloat16(v.w - __bfloat162float(h3));
    reinterpret_cast<__nv_bfloat162*>(g_xh + i)[0] = __halves2bfloat162(h0, h1);
    reinterpret_cast<__nv_bfloat162*>(g_xh + i)[1] = __halves2bfloat162(h2, h3);
    reinterpret_cast<__nv_bfloat162*>(g_xl + i)[0] = __halves2bfloat162(l0, l1);
    reinterpret_cast<__nv_bfloat162*>(g_xl + i)[1] = __halves2bfloat162(l2, l3);
}

// ---------------------------------------------------------------------------
// Prep 2: W [K,N] -> W^T hi/lo [N,K]
// ---------------------------------------------------------------------------
__global__ __launch_bounds__(256) void conv_wt(const float* __restrict__ W) {
    __shared__ float tile[32][33];
    const int n0 = blockIdx.x * 32, k0 = blockIdx.y * 32;
    const int tx = threadIdx.x, ty = threadIdx.y;   // (32, 8)
#pragma unroll
    for (int i = 0; i < 4; ++i)
        tile[ty + 8 * i][tx] = W[(size_t)(k0 + ty + 8 * i) * NQKV + n0 + tx];
    __syncthreads();
#pragma unroll
    for (int i = 0; i < 4; ++i) {
        int n = ty + 8 * i;
        float v = tile[tx][n];
        __nv_bfloat16 h = __float2bfloat16(v);
        __nv_bfloat16 l = __float2bfloat16(v - __bfloat162float(h));
        g_wth[(size_t)(n0 + n) * HIDDEN + k0 + tx] = h;
        g_wtl[(size_t)(n0 + n) * HIDDEN + k0 + tx] = l;
    }
}

// ---------------------------------------------------------------------------
// mma.sync bf16 GEMM (as round 4, passing), epilogue now writes bf16 hi/lo
// ---------------------------------------------------------------------------
#define PLANE 10240
#define BUFSZ (4 * PLANE)
#define GM_SMEM_TOTAL (2 * BUFSZ)

__global__ __launch_bounds__(256, 1) void qkv_gemm_tc(const float* __restrict__ bias) {
    extern __shared__ char smem[];
    const uint32_t sb = smem_u32(smem);
    const int tid = threadIdx.x;
    const int wid = tid >> 5, lane = tid & 31;
    const int bn = blockIdx.x << 7, bm = blockIdx.y << 7;

    const int wmb = (wid & 1) << 6;
    const int wnb = (wid >> 1) << 5;

    float acc[4][4][4];
#pragma unroll
    for (int mt = 0; mt < 4; ++mt)
#pragma unroll
        for (int nt = 0; nt < 4; ++nt)
#pragma unroll
            for (int q = 0; q < 4; ++q) acc[mt][nt][q] = 0.0f;

    auto load_chunk = [&](int c) {
        const int b = c & 1;
        const int k0 = c << 5;
        const uint32_t base = sb + b * BUFSZ;
#pragma unroll
        for (int i = 0; i < 8; ++i) {
            const int f = tid + (i << 8);
            const int t = f >> 9;
            const int rc = f & 511;
            const int r = rc >> 2, j = rc & 3;
            const __nv_bfloat16* src;
            if (t == 0)      src = g_xh  + (size_t)(bm + r) * HIDDEN + k0 + j * 8;
            else if (t == 1) src = g_xl  + (size_t)(bm + r) * HIDDEN + k0 + j * 8;
            else if (t == 2) src = g_wth + (size_t)(bn + r) * HIDDEN + k0 + j * 8;
            else             src = g_wtl + (size_t)(bn + r) * HIDDEN + k0 + j * 8;
            CP_ASYNC16(base + t * PLANE + r * 80 + j * 16, src);
        }
        CP_COMMIT();
    };

    load_chunk(0);
    load_chunk(1);

    const int arow = wmb + (lane & 15);
    const int akoff = (lane >> 4) << 4;
    const int brow = wnb + ((lane >> 4) << 3) + (lane & 7);
    const int bkoff = ((lane >> 3) & 1) << 4;

    for (int c = 0; c < 64; ++c) {
        const int b = c & 1;
        if (c == 63) { CP_WAIT0(); } else { CP_WAIT1(); }
        __syncthreads();
        const uint32_t Ah = sb + b * BUFSZ;
        const uint32_t Al = Ah + PLANE;
        const uint32_t Bh = Al + PLANE;
        const uint32_t Bl = Bh + PLANE;
#pragma unroll
        for (int s = 0; s < 2; ++s) {
            uint32_t ah[4][4], al[4][4], bh[2][4], bl[2][4];
            const int sk = s << 5;
#pragma unroll
            for (int mt = 0; mt < 4; ++mt) {
                const uint32_t off = (uint32_t)((arow + (mt << 4)) * 80) + akoff + sk;
                ldsm4(ah[mt], Ah + off);
                ldsm4(al[mt], Al + off);
            }
#pragma unroll
            for (int p = 0; p < 2; ++p) {
                const uint32_t off = (uint32_t)((brow + (p << 4)) * 80) + bkoff + sk;
                ldsm4(bh[p], Bh + off);
                ldsm4(bl[p], Bl + off);
            }
#pragma unroll
            for (int mt = 0; mt < 4; ++mt)
#pragma unroll
                for (int nt = 0; nt < 4; ++nt) {
                    const uint32_t* bhp = &bh[nt >> 1][(nt & 1) * 2];
                    const uint32_t* blp = &bl[nt >> 1][(nt & 1) * 2];
                    mma_bf16(acc[mt][nt], ah[mt], bhp);
                    mma_bf16(acc[mt][nt], ah[mt], blp);
                    mma_bf16(acc[mt][nt], al[mt], bhp);
                }
        }
        __syncthreads();
        if (c + 2 < 64) load_chunk(c + 2);
    }

    // epilogue: add bias, split hi/lo bf16, store
    const int m0 = bm + wmb + (lane >> 2);
    const int n0 = bn + wnb + ((lane & 3) << 1);
#pragma unroll
    for (int mt = 0; mt < 4; ++mt) {
#pragma unroll
        for (int nt = 0; nt < 4; ++nt) {
            const int m = m0 + (mt << 4);
            const int n = n0 + (nt << 3);
            const float b0 = bias[n], b1 = bias[n + 1];
            float v0 = acc[mt][nt][0] + b0, v1 = acc[mt][nt][1] + b1;
            float v2 = acc[mt][nt][2] + b0, v3 = acc[mt][nt][3] + b1;
            uint32_t h01 = packbf2(v0, v1), h23 = packbf2(v2, v3);
            float2 bh01 = __bfloat1622float2(*reinterpret_cast<__nv_bfloat162*>(&h01));
            float2 bh23 = __bfloat1622float2(*reinterpret_cast<__nv_bfloat162*>(&h23));
            uint32_t l01 = packbf2(v0 - bh01.x, v1 - bh01.y);
            uint32_t l23 = packbf2(v2 - bh23.x, v3 - bh23.y);
            *reinterpret_cast<uint32_t*>(&g_qh[(size_t)m * NQKV + n]) = h01;
            *reinterpret_cast<uint32_t*>(&g_ql[(size_t)m * NQKV + n]) = l01;
            *reinterpret_cast<uint32_t*>(&g_qh[(size_t)(m + 8) * NQKV + n]) = h23;
            *reinterpret_cast<uint32_t*>(&g_ql[(size_t)(m + 8) * NQKV + n]) = l23;
        }
    }
}

// ---------------------------------------------------------------------------
// Tensor-core flash attention. 128 thr / 4 warps; q-tile 64, k-tile 64.
// smem planes: Qh Ql Kh Kl Vh Vl, 64 rows x 128 bf16, 272B row stride.
// ---------------------------------------------------------------------------
#define AT_STRIDE 272
#define AT_PLANE  (64 * AT_STRIDE)       // 17408
#define AT_SMEM   (6 * AT_PLANE)         // 104448

__global__ __launch_bounds__(128, 1) void attn_tc(const void* __restrict__ lens_raw,
                                                  float* __restrict__ out) {
    extern __shared__ char smem[];
    const uint32_t sb = smem_u32(smem);
    const int b = blockIdx.z, h = blockIdx.y;
    const int q0 = blockIdx.x << 6;
    const int tid = threadIdx.x;
    const int w = tid >> 5, lane = tid & 31;

    const int* li = (const int*)lens_raw;
    int L = (li[1] == 0) ? li[2 * b] : li[b];
    if (L > SEQ) L = SEQ;
    if (L < 0) L = 0;

    float* obase = out + ((size_t)(b * HEADS + h) * SEQ) * HD;

    if (q0 >= L) {
        float4 z = make_float4(0.f, 0.f, 0.f, 0.f);
        for (int f = tid; f < 64 * 32; f += 128) {
            int r = f >> 5, c4 = (f & 31) << 2;
            *reinterpret_cast<float4*>(&obase[(size_t)(q0 + r) * HD + c4]) = z;
        }
        return;
    }

    const size_t rowbase = (size_t)(b * SEQ) * NQKV + (size_t)h * HD;

    // ---- load Q tile (hi/lo) ----
#pragma unroll
    for (int i = 0; i < 16; ++i) {
        const int f = tid + (i << 7);
        const int pl = f >> 10;              // 0:Qh 1:Ql
        const int rc = f & 1023;
        const int r = rc >> 4, j = rc & 15;
        const __nv_bfloat16* src = (pl ? g_ql : g_qh) + rowbase + (size_t)(q0 + r) * NQKV + j * 8;
        CP_ASYNC16(sb + pl * AT_PLANE + r * AT_STRIDE + j * 16, src);
    }
    CP_COMMIT();

    auto load_kv = [&](int t) {
        const int k0 = t << 6;
#pragma unroll
        for (int i = 0; i < 32; ++i) {
            const int f = tid + (i << 7);
            const int pl = f >> 10;          // 0:Kh 1:Kl 2:Vh 3:Vl
            const int rc = f & 1023;
            const int r = rc >> 4, j = rc & 15;
            const int colb = (pl < 2) ? HIDDEN : 2 * HIDDEN;
            const __nv_bfloat16* base = (pl & 1) ? g_ql : g_qh;
            const __nv_bfloat16* src = base + rowbase + (size_t)(k0 + r) * NQKV + colb + j * 8;
            CP_ASYNC16(sb + (2 + pl) * AT_PLANE + r * AT_STRIDE + j * 16, src);
        }
        CP_COMMIT();
    };

    load_kv(0);
    CP_WAIT0();
    __syncthreads();

    float accO[16][4];
#pragma unroll
    for (int j = 0; j < 16; ++j)
#pragma unroll
        for (int q = 0; q < 4; ++q) accO[j][q] = 0.0f;
    float m0 = -1e30f, m1 = -1e30f, l0 = 0.0f, l1 = 0.0f;
    const float scale = 0.088388347648318447f;

    // ldmatrix lane addressing
    const uint32_t aoff = (uint32_t)((w * 16 + (lane & 15)) * AT_STRIDE) + ((lane >> 4) << 4);
    const uint32_t bO   = (uint32_t)((((lane >> 4) << 3) + (lane & 7)) * AT_STRIDE) +
                          (((lane >> 3) & 1) << 4);
    const uint32_t voff = (uint32_t)((lane & 15) * AT_STRIDE) + ((lane >> 4) << 4);

    const int nkt = (L + 63) >> 6;
    for (int t = 0; t < nkt; ++t) {
        const int k0 = t << 6;

        // ---- scores: S = Qhi*Khi + Qhi*Klo + Qlo*Khi (m16 x n64 x k128) ----
        float sc[8][4];
#pragma unroll
        for (int j = 0; j < 8; ++j)
#pragma unroll
            for (int q = 0; q < 4; ++q) sc[j][q] = 0.0f;

#pragma unroll
        for (int s = 0; s < 8; ++s) {
            const uint32_t sk = (uint32_t)(s << 5);
            uint32_t ah[4], al[4];
            ldsm4(ah, sb + 0 * AT_PLANE + aoff + sk);
            ldsm4(al, sb + 1 * AT_PLANE + aoff + sk);
#pragma unroll
            for (int p = 0; p < 4; ++p) {
                uint32_t bh[4], bl[4];
                const uint32_t boff = (uint32_t)(p * 16 * AT_STRIDE) + bO + sk;
                ldsm4(bh, sb + 2 * AT_PLANE + boff);
                ldsm4(bl, sb + 3 * AT_PLANE + boff);
                mma_bf16(sc[2 * p],     ah, &bh[0]);
                mma_bf16(sc[2 * p],     ah, &bl[0]);
                mma_bf16(sc[2 * p],     al, &bh[0]);
                mma_bf16(sc[2 * p + 1], ah, &bh[2]);
                mma_bf16(sc[2 * p + 1], ah, &bl[2]);
                mma_bf16(sc[2 * p + 1], al, &bh[2]);
            }
        }

        // ---- scale + mask ----
        const int cbase = k0 + ((lane & 3) << 1);
#pragma unroll
        for (int j = 0; j < 8; ++j) {
            const int c0 = cbase + 8 * j;
            const bool v0 = c0 < L, v1 = (c0 + 1) < L;
            sc[j][0] = v0 ? sc[j][0] * scale : -1e30f;
            sc[j][1] = v1 ? sc[j][1] * scale : -1e30f;
            sc[j][2] = v0 ? sc[j][2] * scale : -1e30f;
            sc[j][3] = v1 ? sc[j][3] * scale : -1e30f;
        }

        // ---- online softmax (two row-halves per thread) ----
        float tm0 = -1e30f, tm1 = -1e30f;
#pragma unroll
        for (int j = 0; j < 8; ++j) {
            tm0 = fmaxf(tm0, fmaxf(sc[j][0], sc[j][1]));
            tm1 = fmaxf(tm1, fmaxf(sc[j][2], sc[j][3]));
        }
        tm0 = fmaxf(tm0, __shfl_xor_sync(0xffffffffu, tm0, 1));
        tm0 = fmaxf(tm0, __shfl_xor_sync(0xffffffffu, tm0, 2));
        tm1 = fmaxf(tm1, __shfl_xor_sync(0xffffffffu, tm1, 1));
        tm1 = fmaxf(tm1, __shfl_xor_sync(0xffffffffu, tm1, 2));
        const float mn0 = fmaxf(m0, tm0), mn1 = fmaxf(m1, tm1);
        const float al0 = __expf(m0 - mn0), al1 = __expf(m1 - mn1);
        m0 = mn0; m1 = mn1;
        float ls0 = 0.0f, ls1 = 0.0f;
#pragma unroll
        for (int j = 0; j < 8; ++j) {
            sc[j][0] = __expf(sc[j][0] - m0);
            sc[j][1] = __expf(sc[j][1] - m0);
            sc[j][2] = __expf(sc[j][2] - m1);
            sc[j][3] = __expf(sc[j][3] - m1);
            ls0 += sc[j][0] + sc[j][1];
            ls1 += sc[j][2] + sc[j][3];
        }
        ls0 += __shfl_xor_sync(0xffffffffu, ls0, 1);
        ls0 += __shfl_xor_sync(0xffffffffu, ls0, 2);
        ls1 += __shfl_xor_sync(0xffffffffu, ls1, 1);
        ls1 += __shfl_xor_sync(0xffffffffu, ls1, 2);
        l0 = l0 * al0 + ls0;
        l1 = l1 * al1 + ls1;
#pragma unroll
        for (int j = 0; j < 16; ++j) {
            accO[j][0] *= al0; accO[j][1] *= al0;
            accO[j][2] *= al1; accO[j][3] *= al1;
        }

        // ---- O += P @ V (P hi/lo from registers, V hi/lo via ldmatrix.trans) ----
#pragma unroll
        for (int ks = 0; ks < 4; ++ks) {
            const int j0 = 2 * ks, j1 = 2 * ks + 1;
            uint32_t aH[4], aL[4];
            aH[0] = packbf2(sc[j0][0], sc[j0][1]);
            aH[1] = packbf2(sc[j0][2], sc[j0][3]);
            aH[2] = packbf2(sc[j1][0], sc[j1][1]);
            aH[3] = packbf2(sc[j1][2], sc[j1][3]);
#pragma unroll
            for (int q = 0; q < 4; ++q) {
                const int jj = (q < 2) ? j0 : j1;
                const int qq = (q & 1) << 1;
                float2 bk = __bfloat1622float2(*reinterpret_cast<__nv_bfloat162*>(&aH[q]));
                aL[q] = packbf2(sc[jj][qq] - bk.x, sc[jj][qq + 1] - bk.y);
            }
            const uint32_t vrow = (uint32_t)(ks * 16 * AT_STRIDE) + voff;
#pragma unroll
            for (int dd = 0; dd < 8; ++dd) {
                uint32_t vh[4], vl[4];
                const uint32_t va = vrow + (uint32_t)(dd << 5);
                ldsm4t(vh, sb + 4 * AT_PLANE + va);
                ldsm4t(vl, sb + 5 * AT_PLANE + va);
                mma_bf16(accO[2 * dd],     aH, &vh[0]);
                mma_bf16(accO[2 * dd],     aH, &vl[0]);
                mma_bf16(accO[2 * dd],     aL, &vh[0]);
                mma_bf16(accO[2 * dd + 1], aH, &vh[2]);
                mma_bf16(accO[2 * dd + 1], aH, &vl[2]);
                mma_bf16(accO[2 * dd + 1], aL, &vh[2]);
            }
        }

        __syncthreads();                 // done reading K/V smem
        if (t + 1 < nkt) {
            load_kv(t + 1);
            CP_WAIT0();
            __syncthreads();
        }
    }

    // ---- epilogue ----
    const float inv0 = 1.0f / l0, inv1 = 1.0f / l1;
    const int r0 = q0 + w * 16 + (lane >> 2);
    const int r1 = r0 + 8;
    const bool v0 = r0 < L, v1 = r1 < L;
    const int dbase = (lane & 3) << 1;
#pragma unroll
    for (int j = 0; j < 16; ++j) {
        const int d = dbase + 8 * j;
        float2 o0 = v0 ? make_float2(accO[j][0] * inv0, accO[j][1] * inv0)
                       : make_float2(0.f, 0.f);
        float2 o1 = v1 ? make_float2(accO[j][2] * inv1, accO[j][3] * inv1)
                       : make_float2(0.f, 0.f);
        *reinterpret_cast<float2*>(&obase[(size_t)r0 * HD + d]) = o0;
        *reinterpret_cast<float2*>(&obase[(size_t)r1 * HD + d]) = o1;
    }
}

// ---------------------------------------------------------------------------
extern "C" void kernel_launch(void* const* d_in, const int* in_sizes, int n_in,
                              void* d_out, int out_size) {
    const float* x    = (const float*)d_in[0];   // [4, 2048, 2048]
    const float* W    = (const float*)d_in[1];   // [2048, 6144]
    const float* bias = (const float*)d_in[2];   // [6144]
    const void*  lens = d_in[3];                 // [4] int64 (or int32)
    float* out = (float*)d_out;                  // [4, 16, 2048, 128]

    cudaFuncSetAttribute(qkv_gemm_tc, cudaFuncAttributeMaxDynamicSharedMemorySize,
                         GM_SMEM_TOTAL);
    cudaFuncSetAttribute(attn_tc, cudaFuncAttributeMaxDynamicSharedMemorySize,
                         AT_SMEM);

    conv_x<<<(MTOT * HIDDEN) / (256 * 4), 256>>>(x);
    conv_wt<<<dim3(NQKV / 32, HIDDEN / 32), dim3(32, 8)>>>(W);
    qkv_gemm_tc<<<dim3(NQKV / 128, MTOT / 128), 256, GM_SMEM_TOTAL>>>(bias);
    attn_tc<<<dim3(SEQ / 64, HEADS, BB), 128, AT_SMEM>>>(lens, out);
}

// round 6
// speedup vs baseline: 2.7326x; 1.0382x over previous
#include <cuda_runtime.h>
#include <cuda_bf16.h>
#include <cstdint>

#define HEADS  16
#define HD     128
#define HIDDEN 2048
#define BB     4
#define SEQ    2048
#define NQKV   (3*HIDDEN)      // 6144
#define MTOT   (BB*SEQ)        // 8192

// ---------------------------------------------------------------------------
// Scratch (device globals; no allocation allowed)
// ---------------------------------------------------------------------------
__device__ __nv_bfloat16 g_qh[(size_t)MTOT * NQKV];           // qkv hi plane
__device__ __nv_bfloat16 g_ql[(size_t)MTOT * NQKV];           // qkv lo plane
__device__ __nv_bfloat16 g_xh[(size_t)MTOT * HIDDEN];         // x hi
__device__ __nv_bfloat16 g_xl[(size_t)MTOT * HIDDEN];         // x lo
__device__ __nv_bfloat16 g_wth[(size_t)NQKV * HIDDEN];        // W^T hi [N,K]
__device__ __nv_bfloat16 g_wtl[(size_t)NQKV * HIDDEN];        // W^T lo [N,K]

// ---------------------------------------------------------------------------
// sm_80-level tensor-core primitives (valid on plain sm_103 target)
// ---------------------------------------------------------------------------
__device__ __forceinline__ uint32_t smem_u32(const void* p) {
    uint32_t a;
    asm("{ .reg .u64 t; cvta.to.shared.u64 t, %1; cvt.u32.u64 %0, t; }" : "=r"(a) : "l"(p));
    return a;
}
__device__ __forceinline__ void ldsm4(uint32_t* r, uint32_t addr) {
    asm volatile("ldmatrix.sync.aligned.m8n8.x4.shared.b16 {%0,%1,%2,%3}, [%4];"
        : "=r"(r[0]), "=r"(r[1]), "=r"(r[2]), "=r"(r[3]) : "r"(addr));
}
__device__ __forceinline__ void ldsm4t(uint32_t* r, uint32_t addr) {
    asm volatile("ldmatrix.sync.aligned.m8n8.x4.trans.shared.b16 {%0,%1,%2,%3}, [%4];"
        : "=r"(r[0]), "=r"(r[1]), "=r"(r[2]), "=r"(r[3]) : "r"(addr));
}
__device__ __forceinline__ void mma_bf16(float* d, const uint32_t* a, const uint32_t* b) {
    asm volatile("mma.sync.aligned.m16n8k16.row.col.f32.bf16.bf16.f32 "
        "{%0,%1,%2,%3}, {%4,%5,%6,%7}, {%8,%9}, {%0,%1,%2,%3};"
        : "+f"(d[0]), "+f"(d[1]), "+f"(d[2]), "+f"(d[3])
        : "r"(a[0]), "r"(a[1]), "r"(a[2]), "r"(a[3]), "r"(b[0]), "r"(b[1]));
}
#define CP_ASYNC16(dst, src) \
    asm volatile("cp.async.cg.shared.global [%0], [%1], 16;" :: "r"(dst), "l"(src))
#define CP_COMMIT() asm volatile("cp.async.commit_group;" ::: "memory")
#define CP_WAIT2()  asm volatile("cp.async.wait_group 2;" ::: "memory")
#define CP_WAIT1()  asm volatile("cp.async.wait_group 1;" ::: "memory")
#define CP_WAIT0()  asm volatile("cp.async.wait_group 0;" ::: "memory")

__device__ __forceinline__ uint32_t packbf2(float x, float y) {
    __nv_bfloat162 t = __floats2bfloat162_rn(x, y);
    return *reinterpret_cast<uint32_t*>(&t);
}

// ---------------------------------------------------------------------------
// Prep 1: x (fp32) -> hi/lo bf16 planes
// ---------------------------------------------------------------------------
__global__ __launch_bounds__(256) void conv_x(const float* __restrict__ x) {
    size_t i = ((size_t)blockIdx.x * 256 + threadIdx.x) * 4;
    float4 v = *reinterpret_cast<const float4*>(x + i);
    __nv_bfloat16 h0 = __float2bfloat16(v.x), h1 = __float2bfloat16(v.y);
    __nv_bfloat16 h2 = __float2bfloat16(v.z), h3 = __float2bfloat16(v.w);
    __nv_bfloat16 l0 = __float2bfloat16(v.x - __bfloat162float(h0));
    __nv_bfloat16 l1 = __float2bfloat16(v.y - __bfloat162float(h1));
    __nv_bfloat16 l2 = __float2bfloat16(v.z - __bfloat162float(h2));
    __nv_bfloat16 l3 = __float2bfloat16(v.w - __bfloat162float(h3));
    reinterpret_cast<__nv_bfloat162*>(g_xh + i)[0] = __halves2bfloat162(h0, h1);
    reinterpret_cast<__nv_bfloat162*>(g_xh + i)[1] = __halves2bfloat162(h2, h3);
    reinterpret_cast<__nv_bfloat162*>(g_xl + i)[0] = __halves2bfloat162(l0, l1);
    reinterpret_cast<__nv_bfloat162*>(g_xl + i)[1] = __halves2bfloat162(l2, l3);
}

// ---------------------------------------------------------------------------
// Prep 2: W [K,N] -> W^T hi/lo [N,K]
// ---------------------------------------------------------------------------
__global__ __launch_bounds__(256) void conv_wt(const float* __restrict__ W) {
    __shared__ float tile[32][33];
    const int n0 = blockIdx.x * 32, k0 = blockIdx.y * 32;
    const int tx = threadIdx.x, ty = threadIdx.y;   // (32, 8)
#pragma unroll
    for (int i = 0; i < 4; ++i)
        tile[ty + 8 * i][tx] = W[(size_t)(k0 + ty + 8 * i) * NQKV + n0 + tx];
    __syncthreads();
#pragma unroll
    for (int i = 0; i < 4; ++i) {
        int n = ty + 8 * i;
        float v = tile[tx][n];
        __nv_bfloat16 h = __float2bfloat16(v);
        __nv_bfloat16 l = __float2bfloat16(v - __bfloat162float(h));
        g_wth[(size_t)(n0 + n) * HIDDEN + k0 + tx] = h;
        g_wtl[(size_t)(n0 + n) * HIDDEN + k0 + tx] = l;
    }
}

// ---------------------------------------------------------------------------
// mma.sync bf16 GEMM v2: CTA 256x128, 512 thr / 16 warps (each m64 x n32),
// k-chunk 32, 3-stage cp.async pipeline, 80B smem row stride.
// Stage layout: Ah(256x80) | Al(256x80) | Bh(128x80) | Bl(128x80)
// ---------------------------------------------------------------------------
#define GA_PL  20480                 // A plane: 256 * 80
#define GB_PL  10240                 // B plane: 128 * 80
#define STAGE  (2*GA_PL + 2*GB_PL)   // 61440
#define GM_SMEM_TOTAL (3 * STAGE)    // 184320

__global__ __launch_bounds__(512, 1) void qkv_gemm_tc(const float* __restrict__ bias) {
    extern __shared__ char smem[];
    const uint32_t sb = smem_u32(smem);
    const int tid = threadIdx.x;
    const int wid = tid >> 5, lane = tid & 31;
    const int bn = blockIdx.x << 7, bm = blockIdx.y << 8;

    const int wmb = (wid & 3) << 6;     // warp m base: 0/64/128/192
    const int wnb = (wid >> 2) << 5;    // warp n base: 0/32/64/96

    float acc[4][4][4];
#pragma unroll
    for (int mt = 0; mt < 4; ++mt)
#pragma unroll
        for (int nt = 0; nt < 4; ++nt)
#pragma unroll
            for (int q = 0; q < 4; ++q) acc[mt][nt][q] = 0.0f;

    // ---- async loader: chunk c (32 bf16 of K) into stage c%3 ----
    auto load_chunk = [&](int c) {
        const uint32_t base = sb + (uint32_t)(c % 3) * STAGE;
        const int k0 = c << 5;
#pragma unroll
        for (int i = 0; i < 6; ++i) {
            const int f = tid + (i << 9);            // 0..3071
            if (f < 2048) {                          // A planes: 2 x 256 rows x 4
                const int pl = f >> 10;              // 0:Ah 1:Al
                const int rc = f & 1023;
                const int r = rc >> 2, j = rc & 3;
                const __nv_bfloat16* src =
                    (pl ? g_xl : g_xh) + (size_t)(bm + r) * HIDDEN + k0 + j * 8;
                CP_ASYNC16(base + pl * GA_PL + r * 80 + j * 16, src);
            } else {                                 // B planes: 2 x 128 rows x 4
                const int g = f - 2048;
                const int pl = g >> 9;               // 0:Bh 1:Bl
                const int rc = g & 511;
                const int r = rc >> 2, j = rc & 3;
                const __nv_bfloat16* src =
                    (pl ? g_wtl : g_wth) + (size_t)(bn + r) * HIDDEN + k0 + j * 8;
                CP_ASYNC16(base + 2 * GA_PL + pl * GB_PL + r * 80 + j * 16, src);
            }
        }
        CP_COMMIT();
    };

    load_chunk(0);
    load_chunk(1);
    load_chunk(2);

    // ldmatrix lane addressing (byte offsets within plane; validated in R4)
    const int arow = wmb + (lane & 15);
    const int akoff = (lane >> 4) << 4;
    const int brow = wnb + ((lane >> 4) << 3) + (lane & 7);
    const int bkoff = ((lane >> 3) & 1) << 4;

    for (int c = 0; c < 64; ++c) {
        if (c < 62) { CP_WAIT2(); } else if (c == 62) { CP_WAIT1(); } else { CP_WAIT0(); }
        __syncthreads();
        const uint32_t Ah = sb + (uint32_t)(c % 3) * STAGE;
        const uint32_t Al = Ah + GA_PL;
        const uint32_t Bh = Al + GA_PL;
        const uint32_t Bl = Bh + GB_PL;
#pragma unroll
        for (int s = 0; s < 2; ++s) {              // two k16 steps per chunk
            const int sk = s << 5;
            uint32_t ah[4][4], al[4][4];
#pragma unroll
            for (int mt = 0; mt < 4; ++mt) {
                const uint32_t off = (uint32_t)((arow + (mt << 4)) * 80) + akoff + sk;
                ldsm4(ah[mt], Ah + off);
                ldsm4(al[mt], Al + off);
            }
#pragma unroll
            for (int p = 0; p < 2; ++p) {          // each x4 covers 2 n-tiles
                uint32_t bh[4], bl[4];
                const uint32_t off = (uint32_t)((brow + (p << 4)) * 80) + bkoff + sk;
                ldsm4(bh, Bh + off);
                ldsm4(bl, Bl + off);
#pragma unroll
                for (int mt = 0; mt < 4; ++mt)
#pragma unroll
                    for (int half = 0; half < 2; ++half) {
                        const int nt = 2 * p + half;
                        mma_bf16(acc[mt][nt], ah[mt], &bh[half * 2]);   // hi*hi
                        mma_bf16(acc[mt][nt], ah[mt], &bl[half * 2]);   // hi*lo
                        mma_bf16(acc[mt][nt], al[mt], &bh[half * 2]);   // lo*hi
                    }
            }
        }
        __syncthreads();
        if (c + 3 < 64) load_chunk(c + 3);
    }

    // ---- epilogue: add bias, split hi/lo bf16, store ----
    const int m0 = bm + wmb + (lane >> 2);
    const int n0 = bn + wnb + ((lane & 3) << 1);
#pragma unroll
    for (int mt = 0; mt < 4; ++mt) {
#pragma unroll
        for (int nt = 0; nt < 4; ++nt) {
            const int m = m0 + (mt << 4);
            const int n = n0 + (nt << 3);
            const float b0 = bias[n], b1 = bias[n + 1];
            float v0 = acc[mt][nt][0] + b0, v1 = acc[mt][nt][1] + b1;
            float v2 = acc[mt][nt][2] + b0, v3 = acc[mt][nt][3] + b1;
            uint32_t h01 = packbf2(v0, v1), h23 = packbf2(v2, v3);
            float2 bh01 = __bfloat1622float2(*reinterpret_cast<__nv_bfloat162*>(&h01));
            float2 bh23 = __bfloat1622float2(*reinterpret_cast<__nv_bfloat162*>(&h23));
            uint32_t l01 = packbf2(v0 - bh01.x, v1 - bh01.y);
            uint32_t l23 = packbf2(v2 - bh23.x, v3 - bh23.y);
            *reinterpret_cast<uint32_t*>(&g_qh[(size_t)m * NQKV + n]) = h01;
            *reinterpret_cast<uint32_t*>(&g_ql[(size_t)m * NQKV + n]) = l01;
            *reinterpret_cast<uint32_t*>(&g_qh[(size_t)(m + 8) * NQKV + n]) = h23;
            *reinterpret_cast<uint32_t*>(&g_ql[(size_t)(m + 8) * NQKV + n]) = l23;
        }
    }
}

// ---------------------------------------------------------------------------
// Tensor-core flash attention (unchanged, passing at 391us)
// ---------------------------------------------------------------------------
#define AT_STRIDE 272
#define AT_PLANE  (64 * AT_STRIDE)       // 17408
#define AT_SMEM   (6 * AT_PLANE)         // 104448

__global__ __launch_bounds__(128, 1) void attn_tc(const void* __restrict__ lens_raw,
                                                  float* __restrict__ out) {
    extern __shared__ char smem[];
    const uint32_t sb = smem_u32(smem);
    const int b = blockIdx.z, h = blockIdx.y;
    const int q0 = blockIdx.x << 6;
    const int tid = threadIdx.x;
    const int w = tid >> 5, lane = tid & 31;

    const int* li = (const int*)lens_raw;
    int L = (li[1] == 0) ? li[2 * b] : li[b];
    if (L > SEQ) L = SEQ;
    if (L < 0) L = 0;

    float* obase = out + ((size_t)(b * HEADS + h) * SEQ) * HD;

    if (q0 >= L) {
        float4 z = make_float4(0.f, 0.f, 0.f, 0.f);
        for (int f = tid; f < 64 * 32; f += 128) {
            int r = f >> 5, c4 = (f & 31) << 2;
            *reinterpret_cast<float4*>(&obase[(size_t)(q0 + r) * HD + c4]) = z;
        }
        return;
    }

    const size_t rowbase = (size_t)(b * SEQ) * NQKV + (size_t)h * HD;

#pragma unroll
    for (int i = 0; i < 16; ++i) {
        const int f = tid + (i << 7);
        const int pl = f >> 10;
        const int rc = f & 1023;
        const int r = rc >> 4, j = rc & 15;
        const __nv_bfloat16* src = (pl ? g_ql : g_qh) + rowbase + (size_t)(q0 + r) * NQKV + j * 8;
        CP_ASYNC16(sb + pl * AT_PLANE + r * AT_STRIDE + j * 16, src);
    }
    CP_COMMIT();

    auto load_kv = [&](int t) {
        const int k0 = t << 6;
#pragma unroll
        for (int i = 0; i < 32; ++i) {
            const int f = tid + (i << 7);
            const int pl = f >> 10;
            const int rc = f & 1023;
            const int r = rc >> 4, j = rc & 15;
            const int colb = (pl < 2) ? HIDDEN : 2 * HIDDEN;
            const __nv_bfloat16* base = (pl & 1) ? g_ql : g_qh;
            const __nv_bfloat16* src = base + rowbase + (size_t)(k0 + r) * NQKV + colb + j * 8;
            CP_ASYNC16(sb + (2 + pl) * AT_PLANE + r * AT_STRIDE + j * 16, src);
        }
        CP_COMMIT();
    };

    load_kv(0);
    CP_WAIT0();
    __syncthreads();

    float accO[16][4];
#pragma unroll
    for (int j = 0; j < 16; ++j)
#pragma unroll
        for (int q = 0; q < 4; ++q) accO[j][q] = 0.0f;
    float m0 = -1e30f, m1 = -1e30f, l0 = 0.0f, l1 = 0.0f;
    const float scale = 0.088388347648318447f;

    const uint32_t aoff = (uint32_t)((w * 16 + (lane & 15)) * AT_STRIDE) + ((lane >> 4) << 4);
    const uint32_t bO   = (uint32_t)((((lane >> 4) << 3) + (lane & 7)) * AT_STRIDE) +
                          (((lane >> 3) & 1) << 4);
    const uint32_t voff = (uint32_t)((lane & 15) * AT_STRIDE) + ((lane >> 4) << 4);

    const int nkt = (L + 63) >> 6;
    for (int t = 0; t < nkt; ++t) {
        const int k0 = t << 6;

        float sc[8][4];
#pragma unroll
        for (int j = 0; j < 8; ++j)
#pragma unroll
            for (int q = 0; q < 4; ++q) sc[j][q] = 0.0f;

#pragma unroll
        for (int s = 0; s < 8; ++s) {
            const uint32_t sk = (uint32_t)(s << 5);
            uint32_t ah[4], al[4];
            ldsm4(ah, sb + 0 * AT_PLANE + aoff + sk);
            ldsm4(al, sb + 1 * AT_PLANE + aoff + sk);
#pragma unroll
            for (int p = 0; p < 4; ++p) {
                uint32_t bh[4], bl[4];
                const uint32_t boff = (uint32_t)(p * 16 * AT_STRIDE) + bO + sk;
                ldsm4(bh, sb + 2 * AT_PLANE + boff);
                ldsm4(bl, sb + 3 * AT_PLANE + boff);
                mma_bf16(sc[2 * p],     ah, &bh[0]);
                mma_bf16(sc[2 * p],     ah, &bl[0]);
                mma_bf16(sc[2 * p],     al, &bh[0]);
                mma_bf16(sc[2 * p + 1], ah, &bh[2]);
                mma_bf16(sc[2 * p + 1], ah, &bl[2]);
                mma_bf16(sc[2 * p + 1], al, &bh[2]);
            }
        }

        const int cbase = k0 + ((lane & 3) << 1);
#pragma unroll
        for (int j = 0; j < 8; ++j) {
            const int c0 = cbase + 8 * j;
            const bool v0 = c0 < L, v1 = (c0 + 1) < L;
            sc[j][0] = v0 ? sc[j][0] * scale : -1e30f;
            sc[j][1] = v1 ? sc[j][1] * scale : -1e30f;
            sc[j][2] = v0 ? sc[j][2] * scale : -1e30f;
            sc[j][3] = v1 ? sc[j][3] * scale : -1e30f;
        }

        float tm0 = -1e30f, tm1 = -1e30f;
#pragma unroll
        for (int j = 0; j < 8; ++j) {
            tm0 = fmaxf(tm0, fmaxf(sc[j][0], sc[j][1]));
            tm1 = fmaxf(tm1, fmaxf(sc[j][2], sc[j][3]));
        }
        tm0 = fmaxf(tm0, __shfl_xor_sync(0xffffffffu, tm0, 1));
        tm0 = fmaxf(tm0, __shfl_xor_sync(0xffffffffu, tm0, 2));
        tm1 = fmaxf(tm1, __shfl_xor_sync(0xffffffffu, tm1, 1));
        tm1 = fmaxf(tm1, __shfl_xor_sync(0xffffffffu, tm1, 2));
        const float mn0 = fmaxf(m0, tm0), mn1 = fmaxf(m1, tm1);
        const float al0 = __expf(m0 - mn0), al1 = __expf(m1 - mn1);
        m0 = mn0; m1 = mn1;
        float ls0 = 0.0f, ls1 = 0.0f;
#pragma unroll
        for (int j = 0; j < 8; ++j) {
            sc[j][0] = __expf(sc[j][0] - m0);
            sc[j][1] = __expf(sc[j][1] - m0);
            sc[j][2] = __expf(sc[j][2] - m1);
            sc[j][3] = __expf(sc[j][3] - m1);
            ls0 += sc[j][0] + sc[j][1];
            ls1 += sc[j][2] + sc[j][3];
        }
        ls0 += __shfl_xor_sync(0xffffffffu, ls0, 1);
        ls0 += __shfl_xor_sync(0xffffffffu, ls0, 2);
        ls1 += __shfl_xor_sync(0xffffffffu, ls1, 1);
        ls1 += __shfl_xor_sync(0xffffffffu, ls1, 2);
        l0 = l0 * al0 + ls0;
        l1 = l1 * al1 + ls1;
#pragma unroll
        for (int j = 0; j < 16; ++j) {
            accO[j][0] *= al0; accO[j][1] *= al0;
            accO[j][2] *= al1; accO[j][3] *= al1;
        }

#pragma unroll
        for (int ks = 0; ks < 4; ++ks) {
            const int j0 = 2 * ks, j1 = 2 * ks + 1;
            uint32_t aH[4], aL[4];
            aH[0] = packbf2(sc[j0][0], sc[j0][1]);
            aH[1] = packbf2(sc[j0][2], sc[j0][3]);
            aH[2] = packbf2(sc[j1][0], sc[j1][1]);
            aH[3] = packbf2(sc[j1][2], sc[j1][3]);
#pragma unroll
            for (int q = 0; q < 4; ++q) {
                const int jj = (q < 2) ? j0 : j1;
                const int qq = (q & 1) << 1;
                float2 bk = __bfloat1622float2(*reinterpret_cast<__nv_bfloat162*>(&aH[q]));
                aL[q] = packbf2(sc[jj][qq] - bk.x, sc[jj][qq + 1] - bk.y);
            }
            const uint32_t vrow = (uint32_t)(ks * 16 * AT_STRIDE) + voff;
#pragma unroll
            for (int dd = 0; dd < 8; ++dd) {
                uint32_t vh[4], vl[4];
                const uint32_t va = vrow + (uint32_t)(dd << 5);
                ldsm4t(vh, sb + 4 * AT_PLANE + va);
                ldsm4t(vl, sb + 5 * AT_PLANE + va);
                mma_bf16(accO[2 * dd],     aH, &vh[0]);
                mma_bf16(accO[2 * dd],     aH, &vl[0]);
                mma_bf16(accO[2 * dd],     aL, &vh[0]);
                mma_bf16(accO[2 * dd + 1], aH, &vh[2]);
                mma_bf16(accO[2 * dd + 1], aH, &vl[2]);
                mma_bf16(accO[2 * dd + 1], aL, &vh[2]);
            }
        }

        __syncthreads();
        if (t + 1 < nkt) {
            load_kv(t + 1);
            CP_WAIT0();
            __syncthreads();
        }
    }

    const float inv0 = 1.0f / l0, inv1 = 1.0f / l1;
    const int r0 = q0 + w * 16 + (lane >> 2);
    const int r1 = r0 + 8;
    const bool v0 = r0 < L, v1 = r1 < L;
    const int dbase = (lane & 3) << 1;
#pragma unroll
    for (int j = 0; j < 16; ++j) {
        const int d = dbase + 8 * j;
        float2 o0 = v0 ? make_float2(accO[j][0] * inv0, accO[j][1] * inv0)
                       : make_float2(0.f, 0.f);
        float2 o1 = v1 ? make_float2(accO[j][2] * inv1, accO[j][3] * inv1)
                       : make_float2(0.f, 0.f);
        *reinterpret_cast<float2*>(&obase[(size_t)r0 * HD + d]) = o0;
        *reinterpret_cast<float2*>(&obase[(size_t)r1 * HD + d]) = o1;
    }
}

// ---------------------------------------------------------------------------
extern "C" void kernel_launch(void* const* d_in, const int* in_sizes, int n_in,
                              void* d_out, int out_size) {
    const float* x    = (const float*)d_in[0];   // [4, 2048, 2048]
    const float* W    = (const float*)d_in[1];   // [2048, 6144]
    const float* bias = (const float*)d_in[2];   // [6144]
    const void*  lens = d_in[3];                 // [4] int64 (or int32)
    float* out = (float*)d_out;                  // [4, 16, 2048, 128]

    cudaFuncSetAttribute(qkv_gemm_tc, cudaFuncAttributeMaxDynamicSharedMemorySize,
                         GM_SMEM_TOTAL);
    cudaFuncSetAttribute(attn_tc, cudaFuncAttributeMaxDynamicSharedMemorySize,
                         AT_SMEM);

    conv_x<<<(MTOT * HIDDEN) / (256 * 4), 256>>>(x);
    conv_wt<<<dim3(NQKV / 32, HIDDEN / 32), dim3(32, 8)>>>(W);
    qkv_gemm_tc<<<dim3(NQKV / 128, MTOT / 256), 512, GM_SMEM_TOTAL>>>(bias);
    attn_tc<<<dim3(SEQ / 64, HEADS, BB), 128, AT_SMEM>>>(lens, out);
}

// round 8
// speedup vs baseline: 2.7447x; 1.0044x over previous
#include <cuda_runtime.h>
#include <cuda_bf16.h>
#include <cstdint>

#define HEADS  16
#define HD     128
#define HIDDEN 2048
#define BB     4
#define SEQ    2048
#define NQKV   (3*HIDDEN)      // 6144
#define MTOT   (BB*SEQ)        // 8192

// ---------------------------------------------------------------------------
// Scratch (device globals; no allocation allowed)
// ---------------------------------------------------------------------------
__device__ __nv_bfloat16 g_qh[(size_t)MTOT * NQKV];           // qkv hi plane
__device__ __nv_bfloat16 g_ql[(size_t)MTOT * NQKV];           // qkv lo plane
__device__ __nv_bfloat16 g_xh[(size_t)MTOT * HIDDEN];         // x hi
__device__ __nv_bfloat16 g_xl[(size_t)MTOT * HIDDEN];         // x lo
__device__ __nv_bfloat16 g_wth[(size_t)NQKV * HIDDEN];        // W^T hi [N,K]
__device__ __nv_bfloat16 g_wtl[(size_t)NQKV * HIDDEN];        // W^T lo [N,K]

// ---------------------------------------------------------------------------
// sm_80-level tensor-core primitives (valid on plain sm_103 target)
// ---------------------------------------------------------------------------
__device__ __forceinline__ uint32_t smem_u32(const void* p) {
    uint32_t a;
    asm("{ .reg .u64 t; cvta.to.shared.u64 t, %1; cvt.u32.u64 %0, t; }" : "=r"(a) : "l"(p));
    return a;
}
__device__ __forceinline__ void ldsm4(uint32_t* r, uint32_t addr) {
    asm volatile("ldmatrix.sync.aligned.m8n8.x4.shared.b16 {%0,%1,%2,%3}, [%4];"
        : "=r"(r[0]), "=r"(r[1]), "=r"(r[2]), "=r"(r[3]) : "r"(addr));
}
__device__ __forceinline__ void ldsm4t(uint32_t* r, uint32_t addr) {
    asm volatile("ldmatrix.sync.aligned.m8n8.x4.trans.shared.b16 {%0,%1,%2,%3}, [%4];"
        : "=r"(r[0]), "=r"(r[1]), "=r"(r[2]), "=r"(r[3]) : "r"(addr));
}
__device__ __forceinline__ void mma_bf16(float* d, const uint32_t* a, const uint32_t* b) {
    asm volatile("mma.sync.aligned.m16n8k16.row.col.f32.bf16.bf16.f32 "
        "{%0,%1,%2,%3}, {%4,%5,%6,%7}, {%8,%9}, {%0,%1,%2,%3};"
        : "+f"(d[0]), "+f"(d[1]), "+f"(d[2]), "+f"(d[3])
        : "r"(a[0]), "r"(a[1]), "r"(a[2]), "r"(a[3]), "r"(b[0]), "r"(b[1]));
}
#define CP_ASYNC16(dst, src) \
    asm volatile("cp.async.cg.shared.global [%0], [%1], 16;" :: "r"(dst), "l"(src))
#define CP_COMMIT() asm volatile("cp.async.commit_group;" ::: "memory")
#define CP_WAIT2()  asm volatile("cp.async.wait_group 2;" ::: "memory")
#define CP_WAIT1()  asm volatile("cp.async.wait_group 1;" ::: "memory")
#define CP_WAIT0()  asm volatile("cp.async.wait_group 0;" ::: "memory")

__device__ __forceinline__ uint32_t packbf2(float x, float y) {
    __nv_bfloat162 t = __floats2bfloat162_rn(x, y);
    return *reinterpret_cast<uint32_t*>(&t);
}
__device__ __forceinline__ int get_len(const void* lens_raw, int b) {
    const int* li = (const int*)lens_raw;
    int L = (li[1] == 0) ? li[2 * b] : li[b];   // int64 vs int32 sniff
    if (L > SEQ) L = SEQ;
    if (L < 0) L = 0;
    return L;
}

// ---------------------------------------------------------------------------
// Prep 1: x (fp32) -> hi/lo bf16 planes
// ---------------------------------------------------------------------------
__global__ __launch_bounds__(256) void conv_x(const float* __restrict__ x) {
    size_t i = ((size_t)blockIdx.x * 256 + threadIdx.x) * 4;
    float4 v = *reinterpret_cast<const float4*>(x + i);
    __nv_bfloat16 h0 = __float2bfloat16(v.x), h1 = __float2bfloat16(v.y);
    __nv_bfloat16 h2 = __float2bfloat16(v.z), h3 = __float2bfloat16(v.w);
    __nv_bfloat16 l0 = __float2bfloat16(v.x - __bfloat162float(h0));
    __nv_bfloat16 l1 = __float2bfloat16(v.y - __bfloat162float(h1));
    __nv_bfloat16 l2 = __float2bfloat16(v.z - __bfloat162float(h2));
    __nv_bfloat16 l3 = __float2bfloat16(v.w - __bfloat162float(h3));
    reinterpret_cast<__nv_bfloat162*>(g_xh + i)[0] = __halves2bfloat162(h0, h1);
    reinterpret_cast<__nv_bfloat162*>(g_xh + i)[1] = __halves2bfloat162(h2, h3);
    reinterpret_cast<__nv_bfloat162*>(g_xl + i)[0] = __halves2bfloat162(l0, l1);
    reinterpret_cast<__nv_bfloat162*>(g_xl + i)[1] = __halves2bfloat162(l2, l3);
}

// ---------------------------------------------------------------------------
// Prep 2: W [K,N] -> W^T hi/lo [N,K]
// ---------------------------------------------------------------------------
__global__ __launch_bounds__(256) void conv_wt(const float* __restrict__ W) {
    __shared__ float tile[32][33];
    const int n0 = blockIdx.x * 32, k0 = blockIdx.y * 32;
    const int tx = threadIdx.x, ty = threadIdx.y;   // (32, 8)
#pragma unroll
    for (int i = 0; i < 4; ++i)
        tile[ty + 8 * i][tx] = W[(size_t)(k0 + ty + 8 * i) * NQKV + n0 + tx];
    __syncthreads();
#pragma unroll
    for (int i = 0; i < 4; ++i) {
        int n = ty + 8 * i;
        float v = tile[tx][n];
        __nv_bfloat16 h = __float2bfloat16(v);
        __nv_bfloat16 l = __float2bfloat16(v - __bfloat162float(h));
        g_wth[(size_t)(n0 + n) * HIDDEN + k0 + tx] = h;
        g_wtl[(size_t)(n0 + n) * HIDDEN + k0 + tx] = l;
    }
}

// ---------------------------------------------------------------------------
// mma.sync bf16 GEMM v3: CTA 128x128, 256 thr / 8 warps (m64 x n32 each),
// k-chunk 32, 4-stage cp.async pipeline (single sync per chunk), register
// double-buffered fragments, jagged early-exit on M tiles beyond lengths[b].
// Stage: Ah(128x80) | Al | Bh | Bl  = 40960 B;  4 stages = 163840 B.
// ---------------------------------------------------------------------------
#define GPL   10240                  // plane: 128 rows * 80 B
#define STG   (4 * GPL)              // 40960
#define GM_SMEM_TOTAL (4 * STG)      // 163840

__global__ __launch_bounds__(256, 1) void qkv_gemm_tc(const float* __restrict__ bias,
                                                      const void* __restrict__ lens_raw) {
    const int bm = blockIdx.y << 7;
    // jagged early-exit: rows [bm, bm+127] all beyond this batch's length
    if ((bm & (SEQ - 1)) >= get_len(lens_raw, bm >> 11)) return;

    extern __shared__ char smem[];
    const uint32_t sb = smem_u32(smem);
    const int tid = threadIdx.x;
    const int wid = tid >> 5, lane = tid & 31;
    const int bn = blockIdx.x << 7;

    const int wmb = (wid & 1) << 6;     // warp m base (0/64)
    const int wnb = (wid >> 1) << 5;    // warp n base (0/32/64/96)

    float acc[4][4][4];
#pragma unroll
    for (int mt = 0; mt < 4; ++mt)
#pragma unroll
        for (int nt = 0; nt < 4; ++nt)
#pragma unroll
            for (int q = 0; q < 4; ++q) acc[mt][nt][q] = 0.0f;

    auto load_chunk = [&](int c) {
        const uint32_t base = sb + (uint32_t)(c & 3) * STG;
        const int k0 = c << 5;
#pragma unroll
        for (int i = 0; i < 8; ++i) {
            const int f = tid + (i << 8);          // 0..2047
            const int t = f >> 9;                  // 0:Ah 1:Al 2:Bh 3:Bl
            const int rc = f & 511;
            const int r = rc >> 2, j = rc & 3;
            const __nv_bfloat16* src;
            if (t == 0)      src = g_xh  + (size_t)(bm + r) * HIDDEN + k0 + j * 8;
            else if (t == 1) src = g_xl  + (size_t)(bm + r) * HIDDEN + k0 + j * 8;
            else if (t == 2) src = g_wth + (size_t)(bn + r) * HIDDEN + k0 + j * 8;
            else             src = g_wtl + (size_t)(bn + r) * HIDDEN + k0 + j * 8;
            CP_ASYNC16(base + t * GPL + r * 80 + j * 16, src);
        }
        CP_COMMIT();
    };

    load_chunk(0);
    load_chunk(1);
    load_chunk(2);

    // ldmatrix lane addressing (validated R4)
    const int arow = wmb + (lane & 15);
    const int akoff = (lane >> 4) << 4;
    const int brow = wnb + ((lane >> 4) << 3) + (lane & 7);
    const int bkoff = ((lane >> 3) & 1) << 4;

    for (int c = 0; c < 64; ++c) {
        if (c < 62) { CP_WAIT2(); } else if (c == 62) { CP_WAIT1(); } else { CP_WAIT0(); }
        __syncthreads();
        if (c + 3 < 64) load_chunk(c + 3);   // stage (c+3)&3 == (c-1)&3, reads done

        const uint32_t stg = sb + (uint32_t)(c & 3) * STG;
        uint32_t ah[2][4][4], al[2][4][4], bh[2][2][4], bl[2][2][4];

        // fragment load for k16 step s into buffer buf
#define LDFRAGS(buf, s) do {                                                    \
        const int sk_ = (s) << 5;                                               \
        _Pragma("unroll")                                                       \
        for (int mt = 0; mt < 4; ++mt) {                                        \
            const uint32_t off = (uint32_t)((arow + (mt << 4)) * 80) + akoff + sk_; \
            ldsm4(ah[buf][mt], stg + off);                                      \
            ldsm4(al[buf][mt], stg + GPL + off);                                \
        }                                                                       \
        _Pragma("unroll")                                                       \
        for (int p = 0; p < 2; ++p) {                                           \
            const uint32_t off = (uint32_t)((brow + (p << 4)) * 80) + bkoff + sk_; \
            ldsm4(bh[buf][p], stg + 2 * GPL + off);                             \
            ldsm4(bl[buf][p], stg + 3 * GPL + off);                             \
        }                                                                       \
    } while (0)

        LDFRAGS(0, 0);
        LDFRAGS(1, 1);      // independent of buf0 mma; ptxas interleaves
#pragma unroll
        for (int s = 0; s < 2; ++s) {
#pragma unroll
            for (int mt = 0; mt < 4; ++mt)
#pragma unroll
                for (int p = 0; p < 2; ++p)
#pragma unroll
                    for (int half = 0; half < 2; ++half) {
                        const int nt = 2 * p + half;
                        mma_bf16(acc[mt][nt], ah[s][mt], &bh[s][p][half * 2]);
                        mma_bf16(acc[mt][nt], ah[s][mt], &bl[s][p][half * 2]);
                        mma_bf16(acc[mt][nt], al[s][mt], &bh[s][p][half * 2]);
                    }
        }
#undef LDFRAGS
    }

    // ---- epilogue: add bias, split hi/lo bf16, store ----
    const int m0 = bm + wmb + (lane >> 2);
    const int n0 = bn + wnb + ((lane & 3) << 1);
#pragma unroll
    for (int mt = 0; mt < 4; ++mt) {
#pragma unroll
        for (int nt = 0; nt < 4; ++nt) {
            const int m = m0 + (mt << 4);
            const int n = n0 + (nt << 3);
            const float b0 = bias[n], b1 = bias[n + 1];
            float v0 = acc[mt][nt][0] + b0, v1 = acc[mt][nt][1] + b1;
            float v2 = acc[mt][nt][2] + b0, v3 = acc[mt][nt][3] + b1;
            uint32_t h01 = packbf2(v0, v1), h23 = packbf2(v2, v3);
            float2 bh01 = __bfloat1622float2(*reinterpret_cast<__nv_bfloat162*>(&h01));
            float2 bh23 = __bfloat1622float2(*reinterpret_cast<__nv_bfloat162*>(&h23));
            uint32_t l01 = packbf2(v0 - bh01.x, v1 - bh01.y);
            uint32_t l23 = packbf2(v2 - bh23.x, v3 - bh23.y);
            *reinterpret_cast<uint32_t*>(&g_qh[(size_t)m * NQKV + n]) = h01;
            *reinterpret_cast<uint32_t*>(&g_ql[(size_t)m * NQKV + n]) = l01;
            *reinterpret_cast<uint32_t*>(&g_qh[(size_t)(m + 8) * NQKV + n]) = h23;
            *reinterpret_cast<uint32_t*>(&g_ql[(size_t)(m + 8) * NQKV + n]) = l23;
        }
    }
}

// ---------------------------------------------------------------------------
// Tensor-core flash attention (unchanged, passing at 392us)
// ---------------------------------------------------------------------------
#define AT_STRIDE 272
#define AT_PLANE  (64 * AT_STRIDE)       // 17408
#define AT_SMEM   (6 * AT_PLANE)         // 104448

__global__ __launch_bounds__(128, 1) void attn_tc(const void* __restrict__ lens_raw,
                                                  float* __restrict__ out) {
    extern __shared__ char smem[];
    const uint32_t sb = smem_u32(smem);
    const int b = blockIdx.z, h = blockIdx.y;
    const int q0 = blockIdx.x << 6;
    const int tid = threadIdx.x;
    const int w = tid >> 5, lane = tid & 31;

    const int L = get_len(lens_raw, b);

    float* obase = out + ((size_t)(b * HEADS + h) * SEQ) * HD;

    if (q0 >= L) {
        float4 z = make_float4(0.f, 0.f, 0.f, 0.f);
        for (int f = tid; f < 64 * 32; f += 128) {
            int r = f >> 5, c4 = (f & 31) << 2;
            *reinterpret_cast<float4*>(&obase[(size_t)(q0 + r) * HD + c4]) = z;
        }
        return;
    }

    const size_t rowbase = (size_t)(b * SEQ) * NQKV + (size_t)h * HD;

#pragma unroll
    for (int i = 0; i < 16; ++i) {
        const int f = tid + (i << 7);
        const int pl = f >> 10;
        const int rc = f & 1023;
        const int r = rc >> 4, j = rc & 15;
        const __nv_bfloat16* src = (pl ? g_ql : g_qh) + rowbase + (size_t)(q0 + r) * NQKV + j * 8;
        CP_ASYNC16(sb + pl * AT_PLANE + r * AT_STRIDE + j * 16, src);
    }
    CP_COMMIT();

    auto load_kv = [&](int t) {
        const int k0 = t << 6;
#pragma unroll
        for (int i = 0; i < 32; ++i) {
            const int f = tid + (i << 7);
            const int pl = f >> 10;
            const int rc = f & 1023;
            const int r = rc >> 4, j = rc & 15;
            const int colb = (pl < 2) ? HIDDEN : 2 * HIDDEN;
            const __nv_bfloat16* base = (pl & 1) ? g_ql : g_qh;
            const __nv_bfloat16* src = base + rowbase + (size_t)(k0 + r) * NQKV + colb + j * 8;
            CP_ASYNC16(sb + (2 + pl) * AT_PLANE + r * AT_STRIDE + j * 16, src);
        }
        CP_COMMIT();
    };

    load_kv(0);
    CP_WAIT0();
    __syncthreads();

    float accO[16][4];
#pragma unroll
    for (int j = 0; j < 16; ++j)
#pragma unroll
        for (int q = 0; q < 4; ++q) accO[j][q] = 0.0f;
    float m0 = -1e30f, m1 = -1e30f, l0 = 0.0f, l1 = 0.0f;
    const float scale = 0.088388347648318447f;

    const uint32_t aoff = (uint32_t)((w * 16 + (lane & 15)) * AT_STRIDE) + ((lane >> 4) << 4);
    const uint32_t bO   = (uint32_t)((((lane >> 4) << 3) + (lane & 7)) * AT_STRIDE) +
                          (((lane >> 3) & 1) << 4);
    const uint32_t voff = (uint32_t)((lane & 15) * AT_STRIDE) + ((lane >> 4) << 4);

    const int nkt = (L + 63) >> 6;
    for (int t = 0; t < nkt; ++t) {
        const int k0 = t << 6;

        float sc[8][4];
#pragma unroll
        for (int j = 0; j < 8; ++j)
#pragma unroll
            for (int q = 0; q < 4; ++q) sc[j][q] = 0.0f;

#pragma unroll
        for (int s = 0; s < 8; ++s) {
            const uint32_t sk = (uint32_t)(s << 5);
            uint32_t ah[4], al[4];
            ldsm4(ah, sb + 0 * AT_PLANE + aoff + sk);
            ldsm4(al, sb + 1 * AT_PLANE + aoff + sk);
#pragma unroll
            for (int p = 0; p < 4; ++p) {
                uint32_t bh[4], bl[4];
                const uint32_t boff = (uint32_t)(p * 16 * AT_STRIDE) + bO + sk;
                ldsm4(bh, sb + 2 * AT_PLANE + boff);
                ldsm4(bl, sb + 3 * AT_PLANE + boff);
                mma_bf16(sc[2 * p],     ah, &bh[0]);
                mma_bf16(sc[2 * p],     ah, &bl[0]);
                mma_bf16(sc[2 * p],     al, &bh[0]);
                mma_bf16(sc[2 * p + 1], ah, &bh[2]);
                mma_bf16(sc[2 * p + 1], ah, &bl[2]);
                mma_bf16(sc[2 * p + 1], al, &bh[2]);
            }
        }

        const int cbase = k0 + ((lane & 3) << 1);
#pragma unroll
        for (int j = 0; j < 8; ++j) {
            const int c0 = cbase + 8 * j;
            const bool v0 = c0 < L, v1 = (c0 + 1) < L;
            sc[j][0] = v0 ? sc[j][0] * scale : -1e30f;
            sc[j][1] = v1 ? sc[j][1] * scale : -1e30f;
            sc[j][2] = v0 ? sc[j][2] * scale : -1e30f;
            sc[j][3] = v1 ? sc[j][3] * scale : -1e30f;
        }

        float tm0 = -1e30f, tm1 = -1e30f;
#pragma unroll
        for (int j = 0; j < 8; ++j) {
            tm0 = fmaxf(tm0, fmaxf(sc[j][0], sc[j][1]));
            tm1 = fmaxf(tm1, fmaxf(sc[j][2], sc[j][3]));
        }
        tm0 = fmaxf(tm0, __shfl_xor_sync(0xffffffffu, tm0, 1));
        tm0 = fmaxf(tm0, __shfl_xor_sync(0xffffffffu, tm0, 2));
        tm1 = fmaxf(tm1, __shfl_xor_sync(0xffffffffu, tm1, 1));
        tm1 = fmaxf(tm1, __shfl_xor_sync(0xffffffffu, tm1, 2));
        const float mn0 = fmaxf(m0, tm0), mn1 = fmaxf(m1, tm1);
        const float al0 = __expf(m0 - mn0), al1 = __expf(m1 - mn1);
        m0 = mn0; m1 = mn1;
        float ls0 = 0.0f, ls1 = 0.0f;
#pragma unroll
        for (int j = 0; j < 8; ++j) {
            sc[j][0] = __expf(sc[j][0] - m0);
            sc[j][1] = __expf(sc[j][1] - m0);
            sc[j][2] = __expf(sc[j][2] - m1);
            sc[j][3] = __expf(sc[j][3] - m1);
            ls0 += sc[j][0] + sc[j][1];
            ls1 += sc[j][2] + sc[j][3];
        }
        ls0 += __shfl_xor_sync(0xffffffffu, ls0, 1);
        ls0 += __shfl_xor_sync(0xffffffffu, ls0, 2);
        ls1 += __shfl_xor_sync(0xffffffffu, ls1, 1);
        ls1 += __shfl_xor_sync(0xffffffffu, ls1, 2);
        l0 = l0 * al0 + ls0;
        l1 = l1 * al1 + ls1;
#pragma unroll
        for (int j = 0; j < 16; ++j) {
            accO[j][0] *= al0; accO[j][1] *= al0;
            accO[j][2] *= al1; accO[j][3] *= al1;
        }

#pragma unroll
        for (int ks = 0; ks < 4; ++ks) {
            const int j0 = 2 * ks, j1 = 2 * ks + 1;
            uint32_t aH[4], aL[4];
            aH[0] = packbf2(sc[j0][0], sc[j0][1]);
            aH[1] = packbf2(sc[j0][2], sc[j0][3]);
            aH[2] = packbf2(sc[j1][0], sc[j1][1]);
            aH[3] = packbf2(sc[j1][2], sc[j1][3]);
#pragma unroll
            for (int q = 0; q < 4; ++q) {
                const int jj = (q < 2) ? j0 : j1;
                const int qq = (q & 1) << 1;
                float2 bk = __bfloat1622float2(*reinterpret_cast<__nv_bfloat162*>(&aH[q]));
                aL[q] = packbf2(sc[jj][qq] - bk.x, sc[jj][qq + 1] - bk.y);
            }
            const uint32_t vrow = (uint32_t)(ks * 16 * AT_STRIDE) + voff;
#pragma unroll
            for (int dd = 0; dd < 8; ++dd) {
                uint32_t vh[4], vl[4];
                const uint32_t va = vrow + (uint32_t)(dd << 5);
                ldsm4t(vh, sb + 4 * AT_PLANE + va);
                ldsm4t(vl, sb + 5 * AT_PLANE + va);
                mma_bf16(accO[2 * dd],     aH, &vh[0]);
                mma_bf16(accO[2 * dd],     aH, &vl[0]);
                mma_bf16(accO[2 * dd],     aL, &vh[0]);
                mma_bf16(accO[2 * dd + 1], aH, &vh[2]);
                mma_bf16(accO[2 * dd + 1], aH, &vl[2]);
                mma_bf16(accO[2 * dd + 1], aL, &vh[2]);
            }
        }

        __syncthreads();
        if (t + 1 < nkt) {
            load_kv(t + 1);
            CP_WAIT0();
            __syncthreads();
        }
    }

    const float inv0 = 1.0f / l0, inv1 = 1.0f / l1;
    const int r0 = q0 + w * 16 + (lane >> 2);
    const int r1 = r0 + 8;
    const bool v0 = r0 < L, v1 = r1 < L;
    const int dbase = (lane & 3) << 1;
#pragma unroll
    for (int j = 0; j < 16; ++j) {
        const int d = dbase + 8 * j;
        float2 o0 = v0 ? make_float2(accO[j][0] * inv0, accO[j][1] * inv0)
                       : make_float2(0.f, 0.f);
        float2 o1 = v1 ? make_float2(accO[j][2] * inv1, accO[j][3] * inv1)
                       : make_float2(0.f, 0.f);
        *reinterpret_cast<float2*>(&obase[(size_t)r0 * HD + d]) = o0;
        *reinterpret_cast<float2*>(&obase[(size_t)r1 * HD + d]) = o1;
    }
}

// ---------------------------------------------------------------------------
extern "C" void kernel_launch(void* const* d_in, const int* in_sizes, int n_in,
                              void* d_out, int out_size) {
    const float* x    = (const float*)d_in[0];   // [4, 2048, 2048]
    const float* W    = (const float*)d_in[1];   // [2048, 6144]
    const float* bias = (const float*)d_in[2];   // [6144]
    const void*  lens = d_in[3];                 // [4] int64 (or int32)
    float* out = (float*)d_out;                  // [4, 16, 2048, 128]

    cudaFuncSetAttribute(qkv_gemm_tc, cudaFuncAttributeMaxDynamicSharedMemorySize,
                         GM_SMEM_TOTAL);
    cudaFuncSetAttribute(attn_tc, cudaFuncAttributeMaxDynamicSharedMemorySize,
                         AT_SMEM);

    conv_x<<<(MTOT * HIDDEN) / (256 * 4), 256>>>(x);
    conv_wt<<<dim3(NQKV / 32, HIDDEN / 32), dim3(32, 8)>>>(W);
    qkv_gemm_tc<<<dim3(NQKV / 128, MTOT / 128), 256, GM_SMEM_TOTAL>>>(bias, lens);
    attn_tc<<<dim3(SEQ / 64, HEADS, BB), 128, AT_SMEM>>>(lens, out);
}

// round 11
// speedup vs baseline: 4.1696x; 1.5192x over previous
#include <cuda_runtime.h>
#include <cuda_bf16.h>
#include <cstdint>

#define HEADS  16
#define HD     128
#define HIDDEN 2048
#define BB     4
#define SEQ    2048
#define NQKV   (3*HIDDEN)      // 6144
#define MTOT   (BB*SEQ)        // 8192

// ---------------------------------------------------------------------------
// Scratch (device globals; no allocation allowed)
// ---------------------------------------------------------------------------
__device__ __nv_bfloat16 g_qh[(size_t)MTOT * NQKV];           // qkv hi plane
__device__ __nv_bfloat16 g_ql[(size_t)MTOT * NQKV];           // qkv lo plane
__device__ __nv_bfloat16 g_xh[(size_t)MTOT * HIDDEN];         // x hi
__device__ __nv_bfloat16 g_xl[(size_t)MTOT * HIDDEN];         // x lo
__device__ __nv_bfloat16 g_wth[(size_t)NQKV * HIDDEN];        // W^T hi [N,K]
__device__ __nv_bfloat16 g_wtl[(size_t)NQKV * HIDDEN];        // W^T lo [N,K]

// ---------------------------------------------------------------------------
// sm_80-level tensor-core primitives (valid on plain sm_103 target)
// ---------------------------------------------------------------------------
__device__ __forceinline__ uint32_t smem_u32(const void* p) {
    uint32_t a;
    asm("{ .reg .u64 t; cvta.to.shared.u64 t, %1; cvt.u32.u64 %0, t; }" : "=r"(a) : "l"(p));
    return a;
}
__device__ __forceinline__ void ldsm4(uint32_t* r, uint32_t addr) {
    asm volatile("ldmatrix.sync.aligned.m8n8.x4.shared.b16 {%0,%1,%2,%3}, [%4];"
        : "=r"(r[0]), "=r"(r[1]), "=r"(r[2]), "=r"(r[3]) : "r"(addr));
}
__device__ __forceinline__ void ldsm4t(uint32_t* r, uint32_t addr) {
    asm volatile("ldmatrix.sync.aligned.m8n8.x4.trans.shared.b16 {%0,%1,%2,%3}, [%4];"
        : "=r"(r[0]), "=r"(r[1]), "=r"(r[2]), "=r"(r[3]) : "r"(addr));
}
__device__ __forceinline__ void mma_bf16(float* d, const uint32_t* a, const uint32_t* b) {
    asm volatile("mma.sync.aligned.m16n8k16.row.col.f32.bf16.bf16.f32 "
        "{%0,%1,%2,%3}, {%4,%5,%6,%7}, {%8,%9}, {%0,%1,%2,%3};"
        : "+f"(d[0]), "+f"(d[1]), "+f"(d[2]), "+f"(d[3])
        : "r"(a[0]), "r"(a[1]), "r"(a[2]), "r"(a[3]), "r"(b[0]), "r"(b[1]));
}
#define CP_ASYNC16(dst, src) \
    asm volatile("cp.async.cg.shared.global [%0], [%1], 16;" :: "r"(dst), "l"(src))
#define CP_COMMIT() asm volatile("cp.async.commit_group;" ::: "memory")
#define CP_WAIT2()  asm volatile("cp.async.wait_group 2;" ::: "memory")
#define CP_WAIT1()  asm volatile("cp.async.wait_group 1;" ::: "memory")
#define CP_WAIT0()  asm volatile("cp.async.wait_group 0;" ::: "memory")

__device__ __forceinline__ uint32_t packbf2(float x, float y) {
    __nv_bfloat162 t = __floats2bfloat162_rn(x, y);
    return *reinterpret_cast<uint32_t*>(&t);
}
__device__ __forceinline__ int get_len(const void* lens_raw, int b) {
    const int* li = (const int*)lens_raw;
    int L = (li[1] == 0) ? li[2 * b] : li[b];   // int64 vs int32 sniff
    if (L > SEQ) L = SEQ;
    if (L < 0) L = 0;
    return L;
}

// ---------------------------------------------------------------------------
// Prep 1: x (fp32) -> hi/lo bf16 planes
// ---------------------------------------------------------------------------
__global__ __launch_bounds__(256) void conv_x(const float* __restrict__ x) {
    size_t i = ((size_t)blockIdx.x * 256 + threadIdx.x) * 4;
    float4 v = *reinterpret_cast<const float4*>(x + i);
    __nv_bfloat16 h0 = __float2bfloat16(v.x), h1 = __float2bfloat16(v.y);
    __nv_bfloat16 h2 = __float2bfloat16(v.z), h3 = __float2bfloat16(v.w);
    __nv_bfloat16 l0 = __float2bfloat16(v.x - __bfloat162float(h0));
    __nv_bfloat16 l1 = __float2bfloat16(v.y - __bfloat162float(h1));
    __nv_bfloat16 l2 = __float2bfloat16(v.z - __bfloat162float(h2));
    __nv_bfloat16 l3 = __float2bfloat16(v.w - __bfloat162float(h3));
    reinterpret_cast<__nv_bfloat162*>(g_xh + i)[0] = __halves2bfloat162(h0, h1);
    reinterpret_cast<__nv_bfloat162*>(g_xh + i)[1] = __halves2bfloat162(h2, h3);
    reinterpret_cast<__nv_bfloat162*>(g_xl + i)[0] = __halves2bfloat162(l0, l1);
    reinterpret_cast<__nv_bfloat162*>(g_xl + i)[1] = __halves2bfloat162(l2, l3);
}

// ---------------------------------------------------------------------------
// Prep 2: W [K,N] -> W^T hi/lo [N,K]
// ---------------------------------------------------------------------------
__global__ __launch_bounds__(256) void conv_wt(const float* __restrict__ W) {
    __shared__ float tile[32][33];
    const int n0 = blockIdx.x * 32, k0 = blockIdx.y * 32;
    const int tx = threadIdx.x, ty = threadIdx.y;   // (32, 8)
#pragma unroll
    for (int i = 0; i < 4; ++i)
        tile[ty + 8 * i][tx] = W[(size_t)(k0 + ty + 8 * i) * NQKV + n0 + tx];
    __syncthreads();
#pragma unroll
    for (int i = 0; i < 4; ++i) {
        int n = ty + 8 * i;
        float v = tile[tx][n];
        __nv_bfloat16 h = __float2bfloat16(v);
        __nv_bfloat16 l = __float2bfloat16(v - __bfloat162float(h));
        g_wth[(size_t)(n0 + n) * HIDDEN + k0 + tx] = h;
        g_wtl[(size_t)(n0 + n) * HIDDEN + k0 + tx] = l;
    }
}

// ---------------------------------------------------------------------------
// mma.sync bf16 GEMM v4: CTA 128x128, 512 thr / 16 warps (m32 x n32 each),
// k-chunk 32, 4-stage pipeline, 1 sync/chunk, jagged early-exit.
// Stage: Ah(128x80) | Al | Bh | Bl = 40960 B; 4 stages = 163840 B.
// ---------------------------------------------------------------------------
#define GPL   10240                  // plane: 128 rows * 80 B
#define STG   (4 * GPL)              // 40960
#define GM_SMEM_TOTAL (4 * STG)      // 163840

__global__ __launch_bounds__(512, 1) void qkv_gemm_tc(const float* __restrict__ bias,
                                                      const void* __restrict__ lens_raw) {
    const int bm = blockIdx.y << 7;
    if ((bm & (SEQ - 1)) >= get_len(lens_raw, bm >> 11)) return;   // jagged skip

    extern __shared__ char smem[];
    const uint32_t sb = smem_u32(smem);
    const int tid = threadIdx.x;
    const int wid = tid >> 5, lane = tid & 31;
    const int bn = blockIdx.x << 7;

    const int wmb = (wid & 3) << 5;     // warp m base: 0/32/64/96
    const int wnb = (wid >> 2) << 5;    // warp n base: 0/32/64/96

    float acc[2][4][4];
#pragma unroll
    for (int mt = 0; mt < 2; ++mt)
#pragma unroll
        for (int nt = 0; nt < 4; ++nt)
#pragma unroll
            for (int q = 0; q < 4; ++q) acc[mt][nt][q] = 0.0f;

    auto load_chunk = [&](int c) {
        const uint32_t base = sb + (uint32_t)(c & 3) * STG;
        const int k0 = c << 5;
#pragma unroll
        for (int i = 0; i < 4; ++i) {
            const int f = tid + (i << 9);          // 0..2047
            const int t = f >> 9;                  // 0:Ah 1:Al 2:Bh 3:Bl
            const int rc = f & 511;
            const int r = rc >> 2, j = rc & 3;
            const __nv_bfloat16* src;
            if (t == 0)      src = g_xh  + (size_t)(bm + r) * HIDDEN + k0 + j * 8;
            else if (t == 1) src = g_xl  + (size_t)(bm + r) * HIDDEN + k0 + j * 8;
            else if (t == 2) src = g_wth + (size_t)(bn + r) * HIDDEN + k0 + j * 8;
            else             src = g_wtl + (size_t)(bn + r) * HIDDEN + k0 + j * 8;
            CP_ASYNC16(base + t * GPL + r * 80 + j * 16, src);
        }
        CP_COMMIT();
    };

    load_chunk(0);
    load_chunk(1);
    load_chunk(2);

    // validated ldmatrix lane addressing (R4), mt range now 2
    const int arow = wmb + (lane & 15);
    const int akoff = (lane >> 4) << 4;
    const int brow = wnb + ((lane >> 4) << 3) + (lane & 7);
    const int bkoff = ((lane >> 3) & 1) << 4;

    for (int c = 0; c < 64; ++c) {
        if (c < 62) { CP_WAIT2(); } else if (c == 62) { CP_WAIT1(); } else { CP_WAIT0(); }
        __syncthreads();
        if (c + 3 < 64) load_chunk(c + 3);   // stage (c+3)&3 == (c-1)&3: reads done

        const uint32_t stg = sb + (uint32_t)(c & 3) * STG;
        uint32_t ah[2][2][4], al[2][2][4], bh[2][2][4], bl[2][2][4];

#define LDFRAGS(buf, s) do {                                                    \
        const int sk_ = (s) << 5;                                               \
        _Pragma("unroll")                                                       \
        for (int mt = 0; mt < 2; ++mt) {                                        \
            const uint32_t off = (uint32_t)((arow + (mt << 4)) * 80) + akoff + sk_; \
            ldsm4(ah[buf][mt], stg + off);                                      \
            ldsm4(al[buf][mt], stg + GPL + off);                                \
        }                                                                       \
        _Pragma("unroll")                                                       \
        for (int p = 0; p < 2; ++p) {                                           \
            const uint32_t off = (uint32_t)((brow + (p << 4)) * 80) + bkoff + sk_; \
            ldsm4(bh[buf][p], stg + 2 * GPL + off);                             \
            ldsm4(bl[buf][p], stg + 3 * GPL + off);                             \
        }                                                                       \
    } while (0)

        LDFRAGS(0, 0);
        LDFRAGS(1, 1);
#pragma unroll
        for (int s = 0; s < 2; ++s) {
#pragma unroll
            for (int mt = 0; mt < 2; ++mt)
#pragma unroll
                for (int p = 0; p < 2; ++p)
#pragma unroll
                    for (int half = 0; half < 2; ++half) {
                        const int nt = 2 * p + half;
                        mma_bf16(acc[mt][nt], ah[s][mt], &bh[s][p][half * 2]);
                        mma_bf16(acc[mt][nt], ah[s][mt], &bl[s][p][half * 2]);
                        mma_bf16(acc[mt][nt], al[s][mt], &bh[s][p][half * 2]);
                    }
        }
#undef LDFRAGS
    }

    // ---- epilogue: add bias, split hi/lo bf16, store ----
    const int m0 = bm + wmb + (lane >> 2);
    const int n0 = bn + wnb + ((lane & 3) << 1);
#pragma unroll
    for (int mt = 0; mt < 2; ++mt) {
#pragma unroll
        for (int nt = 0; nt < 4; ++nt) {
            const int m = m0 + (mt << 4);
            const int n = n0 + (nt << 3);
            const float b0 = bias[n], b1 = bias[n + 1];
            float v0 = acc[mt][nt][0] + b0, v1 = acc[mt][nt][1] + b1;
            float v2 = acc[mt][nt][2] + b0, v3 = acc[mt][nt][3] + b1;
            uint32_t h01 = packbf2(v0, v1), h23 = packbf2(v2, v3);
            float2 bh01 = __bfloat1622float2(*reinterpret_cast<__nv_bfloat162*>(&h01));
            float2 bh23 = __bfloat1622float2(*reinterpret_cast<__nv_bfloat162*>(&h23));
            uint32_t l01 = packbf2(v0 - bh01.x, v1 - bh01.y);
            uint32_t l23 = packbf2(v2 - bh23.x, v3 - bh23.y);
            *reinterpret_cast<uint32_t*>(&g_qh[(size_t)m * NQKV + n]) = h01;
            *reinterpret_cast<uint32_t*>(&g_ql[(size_t)m * NQKV + n]) = l01;
            *reinterpret_cast<uint32_t*>(&g_qh[(size_t)(m + 8) * NQKV + n]) = h23;
            *reinterpret_cast<uint32_t*>(&g_ql[(size_t)(m + 8) * NQKV + n]) = l23;
        }
    }
}

// ---------------------------------------------------------------------------
// Tensor-core flash attention v2: q-tile 128 (8 warps / 256 thr), k-tile 64.
// Q planes 128 rows; K/V planes 64 rows; 272B stride (validated).
// ---------------------------------------------------------------------------
#define AT_STRIDE 272
#define AT_QPL (128 * AT_STRIDE)         // 34816
#define AT_KPL (64 * AT_STRIDE)          // 17408
#define SQH 0
#define SQL (AT_QPL)
#define SKH (2 * AT_QPL)
#define SKL (2 * AT_QPL + AT_KPL)
#define SVH (2 * AT_QPL + 2 * AT_KPL)
#define SVL (2 * AT_QPL + 3 * AT_KPL)
#define AT_SMEM (2 * AT_QPL + 4 * AT_KPL)   // 139264

__global__ __launch_bounds__(256, 1) void attn_tc(const void* __restrict__ lens_raw,
                                                  float* __restrict__ out) {
    extern __shared__ char smem[];
    const uint32_t sb = smem_u32(smem);
    const int b = blockIdx.z, h = blockIdx.y;
    const int q0 = blockIdx.x << 7;
    const int tid = threadIdx.x;
    const int w = tid >> 5, lane = tid & 31;

    const int L = get_len(lens_raw, b);

    float* obase = out + ((size_t)(b * HEADS + h) * SEQ) * HD;

    if (q0 >= L) {   // whole 128-row q tile padded -> zeros
        float4 z = make_float4(0.f, 0.f, 0.f, 0.f);
        for (int f = tid; f < 128 * 32; f += 256) {
            int r = f >> 5, c4 = (f & 31) << 2;
            *reinterpret_cast<float4*>(&obase[(size_t)(q0 + r) * HD + c4]) = z;
        }
        return;
    }

    const size_t rowbase = (size_t)(b * SEQ) * NQKV + (size_t)h * HD;

    // ---- load Q tile (hi/lo, 128 rows) ----
#pragma unroll
    for (int i = 0; i < 16; ++i) {
        const int f = tid + (i << 8);        // 0..4095
        const int pl = f >> 11;              // 0:Qh 1:Ql
        const int rc = f & 2047;
        const int r = rc >> 4, j = rc & 15;
        const __nv_bfloat16* src = (pl ? g_ql : g_qh) + rowbase + (size_t)(q0 + r) * NQKV + j * 8;
        CP_ASYNC16(sb + (pl ? SQL : SQH) + r * AT_STRIDE + j * 16, src);
    }
    CP_COMMIT();

    auto load_kv = [&](int t) {
        const int k0 = t << 6;
#pragma unroll
        for (int i = 0; i < 16; ++i) {
            const int f = tid + (i << 8);    // 0..4095
            const int pl = f >> 10;          // 0:Kh 1:Kl 2:Vh 3:Vl
            const int rc = f & 1023;
            const int r = rc >> 4, j = rc & 15;
            const int colb = (pl < 2) ? HIDDEN : 2 * HIDDEN;
            const __nv_bfloat16* base = (pl & 1) ? g_ql : g_qh;
            const __nv_bfloat16* src = base + rowbase + (size_t)(k0 + r) * NQKV + colb + j * 8;
            CP_ASYNC16(sb + SKH + pl * AT_KPL + r * AT_STRIDE + j * 16, src);
        }
        CP_COMMIT();
    };

    load_kv(0);
    CP_WAIT0();
    __syncthreads();

    float accO[16][4];
#pragma unroll
    for (int j = 0; j < 16; ++j)
#pragma unroll
        for (int q = 0; q < 4; ++q) accO[j][q] = 0.0f;
    float m0 = -1e30f, m1 = -1e30f, l0 = 0.0f, l1 = 0.0f;
    const float scale = 0.088388347648318447f;

    const uint32_t aoff = (uint32_t)((w * 16 + (lane & 15)) * AT_STRIDE) + ((lane >> 4) << 4);
    const uint32_t bO   = (uint32_t)((((lane >> 4) << 3) + (lane & 7)) * AT_STRIDE) +
                          (((lane >> 3) & 1) << 4);
    const uint32_t voff = (uint32_t)((lane & 15) * AT_STRIDE) + ((lane >> 4) << 4);

    const int nkt = (L + 63) >> 6;
    for (int t = 0; t < nkt; ++t) {
        const int k0 = t << 6;

        float sc[8][4];
#pragma unroll
        for (int j = 0; j < 8; ++j)
#pragma unroll
            for (int q = 0; q < 4; ++q) sc[j][q] = 0.0f;

#pragma unroll
        for (int s = 0; s < 8; ++s) {
            const uint32_t sk = (uint32_t)(s << 5);
            uint32_t ah[4], al[4];
            ldsm4(ah, sb + SQH + aoff + sk);
            ldsm4(al, sb + SQL + aoff + sk);
#pragma unroll
            for (int p = 0; p < 4; ++p) {
                uint32_t bh[4], bl[4];
                const uint32_t boff = (uint32_t)(p * 16 * AT_STRIDE) + bO + sk;
                ldsm4(bh, sb + SKH + boff);
                ldsm4(bl, sb + SKL + boff);
                mma_bf16(sc[2 * p],     ah, &bh[0]);
                mma_bf16(sc[2 * p],     ah, &bl[0]);
                mma_bf16(sc[2 * p],     al, &bh[0]);
                mma_bf16(sc[2 * p + 1], ah, &bh[2]);
                mma_bf16(sc[2 * p + 1], ah, &bl[2]);
                mma_bf16(sc[2 * p + 1], al, &bh[2]);
            }
        }

        const int cbase = k0 + ((lane & 3) << 1);
#pragma unroll
        for (int j = 0; j < 8; ++j) {
            const int c0 = cbase + 8 * j;
            const bool v0 = c0 < L, v1 = (c0 + 1) < L;
            sc[j][0] = v0 ? sc[j][0] * scale : -1e30f;
            sc[j][1] = v1 ? sc[j][1] * scale : -1e30f;
            sc[j][2] = v0 ? sc[j][2] * scale : -1e30f;
            sc[j][3] = v1 ? sc[j][3] * scale : -1e30f;
        }

        float tm0 = -1e30f, tm1 = -1e30f;
#pragma unroll
        for (int j = 0; j < 8; ++j) {
            tm0 = fmaxf(tm0, fmaxf(sc[j][0], sc[j][1]));
            tm1 = fmaxf(tm1, fmaxf(sc[j][2], sc[j][3]));
        }
        tm0 = fmaxf(tm0, __shfl_xor_sync(0xffffffffu, tm0, 1));
        tm0 = fmaxf(tm0, __shfl_xor_sync(0xffffffffu, tm0, 2));
        tm1 = fmaxf(tm1, __shfl_xor_sync(0xffffffffu, tm1, 1));
        tm1 = fmaxf(tm1, __shfl_xor_sync(0xffffffffu, tm1, 2));
        const float mn0 = fmaxf(m0, tm0), mn1 = fmaxf(m1, tm1);
        const float al0 = __expf(m0 - mn0), al1 = __expf(m1 - mn1);
        m0 = mn0; m1 = mn1;
        float ls0 = 0.0f, ls1 = 0.0f;
#pragma unroll
        for (int j = 0; j < 8; ++j) {
            sc[j][0] = __expf(sc[j][0] - m0);
            sc[j][1] = __expf(sc[j][1] - m0);
            sc[j][2] = __expf(sc[j][2] - m1);
            sc[j][3] = __expf(sc[j][3] - m1);
            ls0 += sc[j][0] + sc[j][1];
            ls1 += sc[j][2] + sc[j][3];
        }
        ls0 += __shfl_xor_sync(0xffffffffu, ls0, 1);
        ls0 += __shfl_xor_sync(0xffffffffu, ls0, 2);
        ls1 += __shfl_xor_sync(0xffffffffu, ls1, 1);
        ls1 += __shfl_xor_sync(0xffffffffu, ls1, 2);
        l0 = l0 * al0 + ls0;
        l1 = l1 * al1 + ls1;
#pragma unroll
        for (int j = 0; j < 16; ++j) {
            accO[j][0] *= al0; accO[j][1] *= al0;
            accO[j][2] *= al1; accO[j][3] *= al1;
        }

#pragma unroll
        for (int ks = 0; ks < 4; ++ks) {
            const int j0 = 2 * ks, j1 = 2 * ks + 1;
            uint32_t aH[4], aL[4];
            aH[0] = packbf2(sc[j0][0], sc[j0][1]);
            aH[1] = packbf2(sc[j0][2], sc[j0][3]);
            aH[2] = packbf2(sc[j1][0], sc[j1][1]);
            aH[3] = packbf2(sc[j1][2], sc[j1][3]);
#pragma unroll
            for (int q = 0; q < 4; ++q) {
                const int jj = (q < 2) ? j0 : j1;
                const int qq = (q & 1) << 1;
                float2 bk = __bfloat1622float2(*reinterpret_cast<__nv_bfloat162*>(&aH[q]));
                aL[q] = packbf2(sc[jj][qq] - bk.x, sc[jj][qq + 1] - bk.y);
            }
            const uint32_t vrow = (uint32_t)(ks * 16 * AT_STRIDE) + voff;
#pragma unroll
            for (int dd = 0; dd < 8; ++dd) {
                uint32_t vh[4], vl[4];
                const uint32_t va = vrow + (uint32_t)(dd << 5);
                ldsm4t(vh, sb + SVH + va);
                ldsm4t(vl, sb + SVL + va);
                mma_bf16(accO[2 * dd],     aH, &vh[0]);
                mma_bf16(accO[2 * dd],     aH, &vl[0]);
                mma_bf16(accO[2 * dd],     aL, &vh[0]);
                mma_bf16(accO[2 * dd + 1], aH, &vh[2]);
                mma_bf16(accO[2 * dd + 1], aH, &vl[2]);
                mma_bf16(accO[2 * dd + 1], aL, &vh[2]);
            }
        }

        __syncthreads();
        if (t + 1 < nkt) {
            load_kv(t + 1);
            CP_WAIT0();
            __syncthreads();
        }
    }

    const float inv0 = 1.0f / l0, inv1 = 1.0f / l1;
    const int r0 = q0 + w * 16 + (lane >> 2);
    const int r1 = r0 + 8;
    const bool v0 = r0 < L, v1 = r1 < L;
    const int dbase = (lane & 3) << 1;
#pragma unroll
    for (int j = 0; j < 16; ++j) {
        const int d = dbase + 8 * j;
        float2 o0 = v0 ? make_float2(accO[j][0] * inv0, accO[j][1] * inv0)
                       : make_float2(0.f, 0.f);
        float2 o1 = v1 ? make_float2(accO[j][2] * inv1, accO[j][3] * inv1)
                       : make_float2(0.f, 0.f);
        *reinterpret_cast<float2*>(&obase[(size_t)r0 * HD + d]) = o0;
        *reinterpret_cast<float2*>(&obase[(size_t)r1 * HD + d]) = o1;
    }
}

// ---------------------------------------------------------------------------
extern "C" void kernel_launch(void* const* d_in, const int* in_sizes, int n_in,
                              void* d_out, int out_size) {
    const float* x    = (const float*)d_in[0];   // [4, 2048, 2048]
    const float* W    = (const float*)d_in[1];   // [2048, 6144]
    const float* bias = (const float*)d_in[2];   // [6144]
    const void*  lens = d_in[3];                 // [4] int64 (or int32)
    float* out = (float*)d_out;                  // [4, 16, 2048, 128]

    cudaFuncSetAttribute(qkv_gemm_tc, cudaFuncAttributeMaxDynamicSharedMemorySize,
                         GM_SMEM_TOTAL);
    cudaFuncSetAttribute(attn_tc, cudaFuncAttributeMaxDynamicSharedMemorySize,
                         AT_SMEM);

    conv_x<<<(MTOT * HIDDEN) / (256 * 4), 256>>>(x);
    conv_wt<<<dim3(NQKV / 32, HIDDEN / 32), dim3(32, 8)>>>(W);
    qkv_gemm_tc<<<dim3(NQKV / 128, MTOT / 128), 512, GM_SMEM_TOTAL>>>(bias, lens);
    attn_tc<<<dim3(SEQ / 128, HEADS, BB), 256, AT_SMEM>>>(lens, out);
}

// round 13
// speedup vs baseline: 4.4063x; 1.0568x over previous
#include <cuda_runtime.h>
#include <cuda_bf16.h>
#include <cstdint>

#define HEADS  16
#define HD     128
#define HIDDEN 2048
#define BB     4
#define SEQ    2048
#define NQKV   (3*HIDDEN)      // 6144
#define MTOT   (BB*SEQ)        // 8192

// ---------------------------------------------------------------------------
// Scratch (device globals; no allocation allowed)
// ---------------------------------------------------------------------------
__device__ __nv_bfloat16 g_qh[(size_t)MTOT * NQKV];           // qkv hi plane
__device__ __nv_bfloat16 g_ql[(size_t)MTOT * NQKV];           // qkv lo plane
__device__ __nv_bfloat16 g_xh[(size_t)MTOT * HIDDEN];         // x hi
__device__ __nv_bfloat16 g_xl[(size_t)MTOT * HIDDEN];         // x lo
__device__ __nv_bfloat16 g_wth[(size_t)NQKV * HIDDEN];        // W^T hi [N,K]
__device__ __nv_bfloat16 g_wtl[(size_t)NQKV * HIDDEN];        // W^T lo [N,K]

// ---------------------------------------------------------------------------
// sm_80-level tensor-core primitives (valid on plain sm_103 target)
// ---------------------------------------------------------------------------
__device__ __forceinline__ uint32_t smem_u32(const void* p) {
    uint32_t a;
    asm("{ .reg .u64 t; cvta.to.shared.u64 t, %1; cvt.u32.u64 %0, t; }" : "=r"(a) : "l"(p));
    return a;
}
__device__ __forceinline__ void ldsm4(uint32_t* r, uint32_t addr) {
    asm volatile("ldmatrix.sync.aligned.m8n8.x4.shared.b16 {%0,%1,%2,%3}, [%4];"
        : "=r"(r[0]), "=r"(r[1]), "=r"(r[2]), "=r"(r[3]) : "r"(addr));
}
__device__ __forceinline__ void ldsm4t(uint32_t* r, uint32_t addr) {
    asm volatile("ldmatrix.sync.aligned.m8n8.x4.trans.shared.b16 {%0,%1,%2,%3}, [%4];"
        : "=r"(r[0]), "=r"(r[1]), "=r"(r[2]), "=r"(r[3]) : "r"(addr));
}
__device__ __forceinline__ void mma_bf16(float* d, const uint32_t* a, const uint32_t* b) {
    asm volatile("mma.sync.aligned.m16n8k16.row.col.f32.bf16.bf16.f32 "
        "{%0,%1,%2,%3}, {%4,%5,%6,%7}, {%8,%9}, {%0,%1,%2,%3};"
        : "+f"(d[0]), "+f"(d[1]), "+f"(d[2]), "+f"(d[3])
        : "r"(a[0]), "r"(a[1]), "r"(a[2]), "r"(a[3]), "r"(b[0]), "r"(b[1]));
}
#define CP_ASYNC16(dst, src) \
    asm volatile("cp.async.cg.shared.global [%0], [%1], 16;" :: "r"(dst), "l"(src))
#define CP_COMMIT() asm volatile("cp.async.commit_group;" ::: "memory")
#define CP_WAIT0()  asm volatile("cp.async.wait_group 0;" ::: "memory")

__device__ __forceinline__ uint32_t packbf2(float x, float y) {
    __nv_bfloat162 t = __floats2bfloat162_rn(x, y);
    return *reinterpret_cast<uint32_t*>(&t);
}
__device__ __forceinline__ int get_len(const void* lens_raw, int b) {
    const int* li = (const int*)lens_raw;
    int L = (li[1] == 0) ? li[2 * b] : li[b];   // int64 vs int32 sniff
    if (L > SEQ) L = SEQ;
    if (L < 0) L = 0;
    return L;
}

// ---------------------------------------------------------------------------
// Prep 1: x (fp32) -> hi/lo bf16 planes
// ---------------------------------------------------------------------------
__global__ __launch_bounds__(256) void conv_x(const float* __restrict__ x) {
    size_t i = ((size_t)blockIdx.x * 256 + threadIdx.x) * 4;
    float4 v = *reinterpret_cast<const float4*>(x + i);
    __nv_bfloat16 h0 = __float2bfloat16(v.x), h1 = __float2bfloat16(v.y);
    __nv_bfloat16 h2 = __float2bfloat16(v.z), h3 = __float2bfloat16(v.w);
    __nv_bfloat16 l0 = __float2bfloat16(v.x - __bfloat162float(h0));
    __nv_bfloat16 l1 = __float2bfloat16(v.y - __bfloat162float(h1));
    __nv_bfloat16 l2 = __float2bfloat16(v.z - __bfloat162float(h2));
    __nv_bfloat16 l3 = __float2bfloat16(v.w - __bfloat162float(h3));
    reinterpret_cast<__nv_bfloat162*>(g_xh + i)[0] = __halves2bfloat162(h0, h1);
    reinterpret_cast<__nv_bfloat162*>(g_xh + i)[1] = __halves2bfloat162(h2, h3);
    reinterpret_cast<__nv_bfloat162*>(g_xl + i)[0] = __halves2bfloat162(l0, l1);
    reinterpret_cast<__nv_bfloat162*>(g_xl + i)[1] = __halves2bfloat162(l2, l3);
}

// ---------------------------------------------------------------------------
// Prep 2: W [K,N] -> W^T hi/lo [N,K]
// ---------------------------------------------------------------------------
__global__ __launch_bounds__(256) void conv_wt(const float* __restrict__ W) {
    __shared__ float tile[32][33];
    const int n0 = blockIdx.x * 32, k0 = blockIdx.y * 32;
    const int tx = threadIdx.x, ty = threadIdx.y;   // (32, 8)
#pragma unroll
    for (int i = 0; i < 4; ++i)
        tile[ty + 8 * i][tx] = W[(size_t)(k0 + ty + 8 * i) * NQKV + n0 + tx];
    __syncthreads();
#pragma unroll
    for (int i = 0; i < 4; ++i) {
        int n = ty + 8 * i;
        float v = tile[tx][n];
        __nv_bfloat16 h = __float2bfloat16(v);
        __nv_bfloat16 l = __float2bfloat16(v - __bfloat162float(h));
        g_wth[(size_t)(n0 + n) * HIDDEN + k0 + tx] = h;
        g_wtl[(size_t)(n0 + n) * HIDDEN + k0 + tx] = l;
    }
}

// ---------------------------------------------------------------------------
// mma.sync bf16 GEMM v5: CTA 128x128, 512 thr / 16 warps (m32 x n32 each),
// 4 stages, 2 chunks per sync window (32 syncs total), jagged early-exit.
// Stage: Ah(128x80) | Al | Bh | Bl = 40960 B; 4 stages = 163840 B.
// ---------------------------------------------------------------------------
#define GPL   10240                  // plane: 128 rows * 80 B
#define STG   (4 * GPL)              // 40960
#define GM_SMEM_TOTAL (4 * STG)      // 163840

__global__ __launch_bounds__(512, 1) void qkv_gemm_tc(const float* __restrict__ bias,
                                                      const void* __restrict__ lens_raw) {
    const int bm = blockIdx.y << 7;
    if ((bm & (SEQ - 1)) >= get_len(lens_raw, bm >> 11)) return;   // jagged skip

    extern __shared__ char smem[];
    const uint32_t sb = smem_u32(smem);
    const int tid = threadIdx.x;
    const int wid = tid >> 5, lane = tid & 31;
    const int bn = blockIdx.x << 7;

    const int wmb = (wid & 3) << 5;     // warp m base: 0/32/64/96
    const int wnb = (wid >> 2) << 5;    // warp n base: 0/32/64/96

    float acc[2][4][4];
#pragma unroll
    for (int mt = 0; mt < 2; ++mt)
#pragma unroll
        for (int nt = 0; nt < 4; ++nt)
#pragma unroll
            for (int q = 0; q < 4; ++q) acc[mt][nt][q] = 0.0f;

    auto load_chunk = [&](int c) {
        const uint32_t base = sb + (uint32_t)(c & 3) * STG;
        const int k0 = c << 5;
#pragma unroll
        for (int i = 0; i < 4; ++i) {
            const int f = tid + (i << 9);          // 0..2047
            const int t = f >> 9;                  // 0:Ah 1:Al 2:Bh 3:Bl
            const int rc = f & 511;
            const int r = rc >> 2, j = rc & 3;
            const __nv_bfloat16* src;
            if (t == 0)      src = g_xh  + (size_t)(bm + r) * HIDDEN + k0 + j * 8;
            else if (t == 1) src = g_xl  + (size_t)(bm + r) * HIDDEN + k0 + j * 8;
            else if (t == 2) src = g_wth + (size_t)(bn + r) * HIDDEN + k0 + j * 8;
            else             src = g_wtl + (size_t)(bn + r) * HIDDEN + k0 + j * 8;
            CP_ASYNC16(base + t * GPL + r * 80 + j * 16, src);
        }
        CP_COMMIT();
    };

    load_chunk(0);
    load_chunk(1);

    // validated ldmatrix lane addressing (R4)
    const int arow = wmb + (lane & 15);
    const int akoff = (lane >> 4) << 4;
    const int brow = wnb + ((lane >> 4) << 3) + (lane & 7);
    const int bkoff = ((lane >> 3) & 1) << 4;

    for (int c = 0; c < 64; c += 2) {
        CP_WAIT0();            // outstanding: chunks c, c+1 only
        __syncthreads();       // also guarantees prior reads of target stages done
        if (c + 2 < 64) load_chunk(c + 2);   // stages (c+2)&3, (c+3)&3 — not read this window
        if (c + 3 < 64) load_chunk(c + 3);

#pragma unroll
        for (int cc = 0; cc < 2; ++cc) {
            const uint32_t stg = sb + (uint32_t)((c + cc) & 3) * STG;
            uint32_t ah[2][2][4], al[2][2][4], bh[2][2][4], bl[2][2][4];

#define LDFRAGS(buf, s) do {                                                    \
            const int sk_ = (s) << 5;                                           \
            _Pragma("unroll")                                                   \
            for (int mt = 0; mt < 2; ++mt) {                                    \
                const uint32_t off = (uint32_t)((arow + (mt << 4)) * 80) + akoff + sk_; \
                ldsm4(ah[buf][mt], stg + off);                                  \
                ldsm4(al[buf][mt], stg + GPL + off);                            \
            }                                                                   \
            _Pragma("unroll")                                                   \
            for (int p = 0; p < 2; ++p) {                                       \
                const uint32_t off = (uint32_t)((brow + (p << 4)) * 80) + bkoff + sk_; \
                ldsm4(bh[buf][p], stg + 2 * GPL + off);                         \
                ldsm4(bl[buf][p], stg + 3 * GPL + off);                         \
            }                                                                   \
        } while (0)

            LDFRAGS(0, 0);
            LDFRAGS(1, 1);
#pragma unroll
            for (int s = 0; s < 2; ++s) {
#pragma unroll
                for (int mt = 0; mt < 2; ++mt)
#pragma unroll
                    for (int p = 0; p < 2; ++p)
#pragma unroll
                        for (int half = 0; half < 2; ++half) {
                            const int nt = 2 * p + half;
                            mma_bf16(acc[mt][nt], ah[s][mt], &bh[s][p][half * 2]);
                            mma_bf16(acc[mt][nt], ah[s][mt], &bl[s][p][half * 2]);
                            mma_bf16(acc[mt][nt], al[s][mt], &bh[s][p][half * 2]);
                        }
            }
#undef LDFRAGS
        }
    }

    // ---- epilogue: add bias, split hi/lo bf16, store ----
    const int m0 = bm + wmb + (lane >> 2);
    const int n0 = bn + wnb + ((lane & 3) << 1);
#pragma unroll
    for (int mt = 0; mt < 2; ++mt) {
#pragma unroll
        for (int nt = 0; nt < 4; ++nt) {
            const int m = m0 + (mt << 4);
            const int n = n0 + (nt << 3);
            const float b0 = bias[n], b1 = bias[n + 1];
            float v0 = acc[mt][nt][0] + b0, v1 = acc[mt][nt][1] + b1;
            float v2 = acc[mt][nt][2] + b0, v3 = acc[mt][nt][3] + b1;
            uint32_t h01 = packbf2(v0, v1), h23 = packbf2(v2, v3);
            float2 bh01 = __bfloat1622float2(*reinterpret_cast<__nv_bfloat162*>(&h01));
            float2 bh23 = __bfloat1622float2(*reinterpret_cast<__nv_bfloat162*>(&h23));
            uint32_t l01 = packbf2(v0 - bh01.x, v1 - bh01.y);
            uint32_t l23 = packbf2(v2 - bh23.x, v3 - bh23.y);
            *reinterpret_cast<uint32_t*>(&g_qh[(size_t)m * NQKV + n]) = h01;
            *reinterpret_cast<uint32_t*>(&g_ql[(size_t)m * NQKV + n]) = l01;
            *reinterpret_cast<uint32_t*>(&g_qh[(size_t)(m + 8) * NQKV + n]) = h23;
            *reinterpret_cast<uint32_t*>(&g_ql[(size_t)(m + 8) * NQKV + n]) = l23;
        }
    }
}

// ---------------------------------------------------------------------------
// Tensor-core flash attention v3: q-tile 128 (8 warps / 256 thr), k-tile 64,
// double-buffered K/V stages (loads overlap compute, 1 sync per tile).
// Q: 2 planes x 128 rows; K/V: 2 stages x 4 planes x 64 rows; 272B stride.
// ---------------------------------------------------------------------------
#define AT_STRIDE 272
#define AT_QPL (128 * AT_STRIDE)         // 34816
#define AT_KPL (64 * AT_STRIDE)          // 17408
#define SQH 0
#define SQL (AT_QPL)
#define SKV0 (2 * AT_QPL)                // K/V stage base
#define KVSTG (4 * AT_KPL)               // 69632 per stage
#define AT_SMEM (2 * AT_QPL + 2 * KVSTG) // 208896

__global__ __launch_bounds__(256, 1) void attn_tc(const void* __restrict__ lens_raw,
                                                  float* __restrict__ out) {
    extern __shared__ char smem[];
    const uint32_t sb = smem_u32(smem);
    const int b = blockIdx.z, h = blockIdx.y;
    const int q0 = blockIdx.x << 7;
    const int tid = threadIdx.x;
    const int w = tid >> 5, lane = tid & 31;

    const int L = get_len(lens_raw, b);

    float* obase = out + ((size_t)(b * HEADS + h) * SEQ) * HD;

    if (q0 >= L) {   // whole 128-row q tile padded -> zeros
        float4 z = make_float4(0.f, 0.f, 0.f, 0.f);
        for (int f = tid; f < 128 * 32; f += 256) {
            int r = f >> 5, c4 = (f & 31) << 2;
            *reinterpret_cast<float4*>(&obase[(size_t)(q0 + r) * HD + c4]) = z;
        }
        return;
    }

    const size_t rowbase = (size_t)(b * SEQ) * NQKV + (size_t)h * HD;

    // ---- load Q tile (hi/lo, 128 rows) ----
#pragma unroll
    for (int i = 0; i < 16; ++i) {
        const int f = tid + (i << 8);        // 0..4095
        const int pl = f >> 11;              // 0:Qh 1:Ql
        const int rc = f & 2047;
        const int r = rc >> 4, j = rc & 15;
        const __nv_bfloat16* src = (pl ? g_ql : g_qh) + rowbase + (size_t)(q0 + r) * NQKV + j * 8;
        CP_ASYNC16(sb + (pl ? SQL : SQH) + r * AT_STRIDE + j * 16, src);
    }
    CP_COMMIT();

    auto load_kv = [&](int t) {
        const int k0 = t << 6;
        const uint32_t stg = sb + SKV0 + (uint32_t)(t & 1) * KVSTG;
#pragma unroll
        for (int i = 0; i < 16; ++i) {
            const int f = tid + (i << 8);    // 0..4095
            const int pl = f >> 10;          // 0:Kh 1:Kl 2:Vh 3:Vl
            const int rc = f & 1023;
            const int r = rc >> 4, j = rc & 15;
            const int colb = (pl < 2) ? HIDDEN : 2 * HIDDEN;
            const __nv_bfloat16* base = (pl & 1) ? g_ql : g_qh;
            const __nv_bfloat16* src = base + rowbase + (size_t)(k0 + r) * NQKV + colb + j * 8;
            CP_ASYNC16(stg + pl * AT_KPL + r * AT_STRIDE + j * 16, src);
        }
        CP_COMMIT();
    };

    load_kv(0);

    float accO[16][4];
#pragma unroll
    for (int j = 0; j < 16; ++j)
#pragma unroll
        for (int q = 0; q < 4; ++q) accO[j][q] = 0.0f;
    float m0 = -1e30f, m1 = -1e30f, l0 = 0.0f, l1 = 0.0f;
    const float scale = 0.088388347648318447f;

    const uint32_t aoff = (uint32_t)((w * 16 + (lane & 15)) * AT_STRIDE) + ((lane >> 4) << 4);
    const uint32_t bO   = (uint32_t)((((lane >> 4) << 3) + (lane & 7)) * AT_STRIDE) +
                          (((lane >> 3) & 1) << 4);
    const uint32_t voff = (uint32_t)((lane & 15) * AT_STRIDE) + ((lane >> 4) << 4);

    const int nkt = (L + 63) >> 6;
    for (int t = 0; t < nkt; ++t) {
        const int k0 = t << 6;

        CP_WAIT0();             // K/V tile t (and Q on t=0) resident
        __syncthreads();        // all warps done reading stage (t+1)&1 (iter t-1)
        if (t + 1 < nkt) load_kv(t + 1);   // overlaps with compute below

        const uint32_t kvs = sb + SKV0 + (uint32_t)(t & 1) * KVSTG;

        // ---- scores: S = Qhi*Khi + Qhi*Klo + Qlo*Khi ----
        float sc[8][4];
#pragma unroll
        for (int j = 0; j < 8; ++j)
#pragma unroll
            for (int q = 0; q < 4; ++q) sc[j][q] = 0.0f;

#pragma unroll
        for (int s = 0; s < 8; ++s) {
            const uint32_t sk = (uint32_t)(s << 5);
            uint32_t ah[4], al[4];
            ldsm4(ah, sb + SQH + aoff + sk);
            ldsm4(al, sb + SQL + aoff + sk);
#pragma unroll
            for (int p = 0; p < 4; ++p) {
                uint32_t bh[4], bl[4];
                const uint32_t boff = (uint32_t)(p * 16 * AT_STRIDE) + bO + sk;
                ldsm4(bh, kvs + boff);
                ldsm4(bl, kvs + AT_KPL + boff);
                mma_bf16(sc[2 * p],     ah, &bh[0]);
                mma_bf16(sc[2 * p],     ah, &bl[0]);
                mma_bf16(sc[2 * p],     al, &bh[0]);
                mma_bf16(sc[2 * p + 1], ah, &bh[2]);
                mma_bf16(sc[2 * p + 1], ah, &bl[2]);
                mma_bf16(sc[2 * p + 1], al, &bh[2]);
            }
        }

        // ---- scale + mask ----
        const int cbase = k0 + ((lane & 3) << 1);
#pragma unroll
        for (int j = 0; j < 8; ++j) {
            const int c0 = cbase + 8 * j;
            const bool v0 = c0 < L, v1 = (c0 + 1) < L;
            sc[j][0] = v0 ? sc[j][0] * scale : -1e30f;
            sc[j][1] = v1 ? sc[j][1] * scale : -1e30f;
            sc[j][2] = v0 ? sc[j][2] * scale : -1e30f;
            sc[j][3] = v1 ? sc[j][3] * scale : -1e30f;
        }

        // ---- online softmax ----
        float tm0 = -1e30f, tm1 = -1e30f;
#pragma unroll
        for (int j = 0; j < 8; ++j) {
            tm0 = fmaxf(tm0, fmaxf(sc[j][0], sc[j][1]));
            tm1 = fmaxf(tm1, fmaxf(sc[j][2], sc[j][3]));
        }
        tm0 = fmaxf(tm0, __shfl_xor_sync(0xffffffffu, tm0, 1));
        tm0 = fmaxf(tm0, __shfl_xor_sync(0xffffffffu, tm0, 2));
        tm1 = fmaxf(tm1, __shfl_xor_sync(0xffffffffu, tm1, 1));
        tm1 = fmaxf(tm1, __shfl_xor_sync(0xffffffffu, tm1, 2));
        const float mn0 = fmaxf(m0, tm0), mn1 = fmaxf(m1, tm1);
        const float al0 = __expf(m0 - mn0), al1 = __expf(m1 - mn1);
        m0 = mn0; m1 = mn1;
        float ls0 = 0.0f, ls1 = 0.0f;
#pragma unroll
        for (int j = 0; j < 8; ++j) {
            sc[j][0] = __expf(sc[j][0] - m0);
            sc[j][1] = __expf(sc[j][1] - m0);
            sc[j][2] = __expf(sc[j][2] - m1);
            sc[j][3] = __expf(sc[j][3] - m1);
            ls0 += sc[j][0] + sc[j][1];
            ls1 += sc[j][2] + sc[j][3];
        }
        ls0 += __shfl_xor_sync(0xffffffffu, ls0, 1);
        ls0 += __shfl_xor_sync(0xffffffffu, ls0, 2);
        ls1 += __shfl_xor_sync(0xffffffffu, ls1, 1);
        ls1 += __shfl_xor_sync(0xffffffffu, ls1, 2);
        l0 = l0 * al0 + ls0;
        l1 = l1 * al1 + ls1;
#pragma unroll
        for (int j = 0; j < 16; ++j) {
            accO[j][0] *= al0; accO[j][1] *= al0;
            accO[j][2] *= al1; accO[j][3] *= al1;
        }

        // ---- O += P @ V ----
#pragma unroll
        for (int ks = 0; ks < 4; ++ks) {
            const int j0 = 2 * ks, j1 = 2 * ks + 1;
            uint32_t aH[4], aL[4];
            aH[0] = packbf2(sc[j0][0], sc[j0][1]);
            aH[1] = packbf2(sc[j0][2], sc[j0][3]);
            aH[2] = packbf2(sc[j1][0], sc[j1][1]);
            aH[3] = packbf2(sc[j1][2], sc[j1][3]);
#pragma unroll
            for (int q = 0; q < 4; ++q) {
                const int jj = (q < 2) ? j0 : j1;
                const int qq = (q & 1) << 1;
                float2 bk = __bfloat1622float2(*reinterpret_cast<__nv_bfloat162*>(&aH[q]));
                aL[q] = packbf2(sc[jj][qq] - bk.x, sc[jj][qq + 1] - bk.y);
            }
            const uint32_t vrow = (uint32_t)(ks * 16 * AT_STRIDE) + voff;
#pragma unroll
            for (int dd = 0; dd < 8; ++dd) {
                uint32_t vh[4], vl[4];
                const uint32_t va = vrow + (uint32_t)(dd << 5);
                ldsm4t(vh, kvs + 2 * AT_KPL + va);
                ldsm4t(vl, kvs + 3 * AT_KPL + va);
                mma_bf16(accO[2 * dd],     aH, &vh[0]);
                mma_bf16(accO[2 * dd],     aH, &vl[0]);
                mma_bf16(accO[2 * dd],     aL, &vh[0]);
                mma_bf16(accO[2 * dd + 1], aH, &vh[2]);
                mma_bf16(accO[2 * dd + 1], aH, &vl[2]);
                mma_bf16(accO[2 * dd + 1], aL, &vh[2]);
            }
        }
    }

    // ---- epilogue ----
    const float inv0 = 1.0f / l0, inv1 = 1.0f / l1;
    const int r0 = q0 + w * 16 + (lane >> 2);
    const int r1 = r0 + 8;
    const bool v0 = r0 < L, v1 = r1 < L;
    const int dbase = (lane & 3) << 1;
#pragma unroll
    for (int j = 0; j < 16; ++j) {
        const int d = dbase + 8 * j;
        float2 o0 = v0 ? make_float2(accO[j][0] * inv0, accO[j][1] * inv0)
                       : make_float2(0.f, 0.f);
        float2 o1 = v1 ? make_float2(accO[j][2] * inv1, accO[j][3] * inv1)
                       : make_float2(0.f, 0.f);
        *reinterpret_cast<float2*>(&obase[(size_t)r0 * HD + d]) = o0;
        *reinterpret_cast<float2*>(&obase[(size_t)r1 * HD + d]) = o1;
    }
}

// ---------------------------------------------------------------------------
extern "C" void kernel_launch(void* const* d_in, const int* in_sizes, int n_in,
                              void* d_out, int out_size) {
    const float* x    = (const float*)d_in[0];   // [4, 2048, 2048]
    const float* W    = (const float*)d_in[1];   // [2048, 6144]
    const float* bias = (const float*)d_in[2];   // [6144]
    const void*  lens = d_in[3];                 // [4] int64 (or int32)
    float* out = (float*)d_out;                  // [4, 16, 2048, 128]

    cudaFuncSetAttribute(qkv_gemm_tc, cudaFuncAttributeMaxDynamicSharedMemorySize,
                         GM_SMEM_TOTAL);
    cudaFuncSetAttribute(attn_tc, cudaFuncAttributeMaxDynamicSharedMemorySize,
                         AT_SMEM);

    conv_x<<<(MTOT * HIDDEN) / (256 * 4), 256>>>(x);
    conv_wt<<<dim3(NQKV / 32, HIDDEN / 32), dim3(32, 8)>>>(W);
    qkv_gemm_tc<<<dim3(NQKV / 128, MTOT / 128), 512, GM_SMEM_TOTAL>>>(bias, lens);
    attn_tc<<<dim3(SEQ / 128, HEADS, BB), 256, AT_SMEM>>>(lens, out);
}